// round 2
// baseline (speedup 1.0000x reference)
#include <cuda_runtime.h>
#include <math.h>

#define EMBED   1024
#define NHEADS  16
#define HD      64
#define BATCH   4
#define SEQ     2048
#define MTOT    (BATCH * SEQ)   // 8192

// ---------------- scratch (static __device__, no allocation) ----------------
__device__ float g_Q[(size_t)MTOT * EMBED];
__device__ float g_K[(size_t)MTOT * EMBED];
__device__ float g_V[(size_t)MTOT * EMBED];
__device__ float g_ctx[(size_t)MTOT * EMBED];

// ---------------- SGEMM + bias: C[M,N] = A[M,K] @ B[K,N] + bias[N] ----------
#define GBM 128
#define GBN 128
#define GBK 8
#define GTM 8
#define GTN 8

__global__ __launch_bounds__(256) void sgemm_bias_kernel(
    const float* __restrict__ A, const float* __restrict__ B,
    const float* __restrict__ bias, float* __restrict__ C,
    int M, int N, int K)
{
    __shared__ float As[GBK][GBM];
    __shared__ float Bs[GBK][GBN];

    const int tid  = threadIdx.x;
    const int brow = blockIdx.y * GBM;
    const int bcol = blockIdx.x * GBN;
    const int trow = (tid / 16) * GTM;
    const int tcol = (tid % 16) * GTN;

    const int a_row = tid >> 1;          // 128 rows, 2 threads/row
    const int a_col = (tid & 1) * 4;     // 0 or 4
    const int b_row = tid >> 5;          // 8 rows
    const int b_col = (tid & 31) * 4;    // 128 cols

    float acc[GTM][GTN];
#pragma unroll
    for (int i = 0; i < GTM; i++)
#pragma unroll
        for (int j = 0; j < GTN; j++) acc[i][j] = 0.0f;

    for (int k0 = 0; k0 < K; k0 += GBK) {
        float4 av = *(const float4*)(&A[(size_t)(brow + a_row) * K + k0 + a_col]);
        As[a_col + 0][a_row] = av.x;
        As[a_col + 1][a_row] = av.y;
        As[a_col + 2][a_row] = av.z;
        As[a_col + 3][a_row] = av.w;
        *(float4*)(&Bs[b_row][b_col]) =
            *(const float4*)(&B[(size_t)(k0 + b_row) * N + bcol + b_col]);
        __syncthreads();

#pragma unroll
        for (int kk = 0; kk < GBK; kk++) {
            float ar[GTM], br[GTN];
#pragma unroll
            for (int i = 0; i < GTM; i++) ar[i] = As[kk][trow + i];
#pragma unroll
            for (int j = 0; j < GTN; j++) br[j] = Bs[kk][tcol + j];
#pragma unroll
            for (int i = 0; i < GTM; i++)
#pragma unroll
                for (int j = 0; j < GTN; j++)
                    acc[i][j] = fmaf(ar[i], br[j], acc[i][j]);
        }
        __syncthreads();
    }

#pragma unroll
    for (int i = 0; i < GTM; i++) {
#pragma unroll
        for (int j = 0; j < GTN; j += 4) {
            float4 o;
            o.x = acc[i][j + 0] + bias[bcol + tcol + j + 0];
            o.y = acc[i][j + 1] + bias[bcol + tcol + j + 1];
            o.z = acc[i][j + 2] + bias[bcol + tcol + j + 2];
            o.w = acc[i][j + 3] + bias[bcol + tcol + j + 3];
            *(float4*)(&C[(size_t)(brow + trow + i) * N + bcol + tcol + j]) = o;
        }
    }
}

// ---------------- Flash attention (fp32, online softmax) --------------------
// Layout: Q/K/V/O are [B*S, E] with head h occupying columns [h*64, h*64+64).
// Block: (q-tile of 64 rows) x (one head) x (one batch), 256 threads.
// Thread (tq = tid/16, tk = tid%16): 4x4 score tile, 4x4 output tile.
#define FBQ  64
#define FBKV 64
#define FPAD 68   // HD + 4 floats to break the row-stride bank pattern

__global__ __launch_bounds__(256) void flash_attn_kernel(
    const float* __restrict__ Q, const float* __restrict__ K,
    const float* __restrict__ V, float* __restrict__ O)
{
    extern __shared__ float smem[];
    float* Qs = smem;                        // [FBQ][FPAD]
    float* Ks = Qs + FBQ * FPAD;             // [FBKV][FPAD]
    float* Vs = Ks + FBKV * FPAD;            // [FBKV][FPAD]
    float* Ps = Vs + FBKV * FPAD;            // [FBQ][FBKV]

    const int tid = threadIdx.x;
    const int h   = blockIdx.y;
    const int b   = blockIdx.z;
    const int q0  = blockIdx.x * FBQ;
    const size_t base = (size_t)b * SEQ * EMBED + (size_t)h * HD;
    const float scale = 0.125f;  // 1/sqrt(64)

    // Load Q tile, pre-scaled
    for (int i = tid; i < FBQ * (HD / 4); i += 256) {
        int r = i >> 4;
        int c = (i & 15) * 4;
        float4 v = *(const float4*)&Q[base + (size_t)(q0 + r) * EMBED + c];
        v.x *= scale; v.y *= scale; v.z *= scale; v.w *= scale;
        *(float4*)&Qs[r * FPAD + c] = v;
    }

    const int tq = tid >> 4;   // 0..15 -> q rows tq*4..tq*4+3
    const int tk = tid & 15;   // 0..15 -> k cols / d cols tk*4..tk*4+3

    float m[4], l[4], acc[4][4];
#pragma unroll
    for (int i = 0; i < 4; i++) {
        m[i] = -1e30f; l[i] = 0.0f;
#pragma unroll
        for (int j = 0; j < 4; j++) acc[i][j] = 0.0f;
    }
    __syncthreads();

    for (int k0 = 0; k0 < SEQ; k0 += FBKV) {
        // Load K,V tiles
        for (int i = tid; i < FBKV * (HD / 4); i += 256) {
            int r = i >> 4;
            int c = (i & 15) * 4;
            *(float4*)&Ks[r * FPAD + c] =
                *(const float4*)&K[base + (size_t)(k0 + r) * EMBED + c];
            *(float4*)&Vs[r * FPAD + c] =
                *(const float4*)&V[base + (size_t)(k0 + r) * EMBED + c];
        }
        __syncthreads();

        // S = Qs @ Ks^T (Q pre-scaled)
        float s[4][4];
#pragma unroll
        for (int i = 0; i < 4; i++)
#pragma unroll
            for (int j = 0; j < 4; j++) s[i][j] = 0.0f;

        for (int d = 0; d < HD; d += 4) {
            float4 qv[4], kv[4];
#pragma unroll
            for (int i = 0; i < 4; i++)
                qv[i] = *(float4*)&Qs[(tq * 4 + i) * FPAD + d];
#pragma unroll
            for (int j = 0; j < 4; j++)
                kv[j] = *(float4*)&Ks[(tk * 4 + j) * FPAD + d];
#pragma unroll
            for (int i = 0; i < 4; i++)
#pragma unroll
                for (int j = 0; j < 4; j++)
                    s[i][j] += qv[i].x * kv[j].x + qv[i].y * kv[j].y
                             + qv[i].z * kv[j].z + qv[i].w * kv[j].w;
        }

        // Online softmax per q-row (row spread across 16 lanes sharing tq)
#pragma unroll
        for (int i = 0; i < 4; i++) {
            float rmax = fmaxf(fmaxf(s[i][0], s[i][1]), fmaxf(s[i][2], s[i][3]));
#pragma unroll
            for (int off = 8; off > 0; off >>= 1)
                rmax = fmaxf(rmax, __shfl_xor_sync(0xffffffffu, rmax, off, 16));
            float mnew = fmaxf(m[i], rmax);
            float corr = __expf(m[i] - mnew);
            float4 p;
            p.x = __expf(s[i][0] - mnew);
            p.y = __expf(s[i][1] - mnew);
            p.z = __expf(s[i][2] - mnew);
            p.w = __expf(s[i][3] - mnew);
            float rsum = p.x + p.y + p.z + p.w;
#pragma unroll
            for (int off = 8; off > 0; off >>= 1)
                rsum += __shfl_xor_sync(0xffffffffu, rsum, off, 16);
            l[i] = l[i] * corr + rsum;
            m[i] = mnew;
            acc[i][0] *= corr; acc[i][1] *= corr;
            acc[i][2] *= corr; acc[i][3] *= corr;
            *(float4*)&Ps[(tq * 4 + i) * FBKV + tk * 4] = p;
        }
        __syncthreads();

        // acc += P @ V  (thread's d columns = tk*4..tk*4+3)
        for (int kk = 0; kk < FBKV; kk += 4) {
            float4 vv[4];
#pragma unroll
            for (int jk = 0; jk < 4; jk++)
                vv[jk] = *(float4*)&Vs[(kk + jk) * FPAD + tk * 4];
#pragma unroll
            for (int i = 0; i < 4; i++) {
                float4 pv = *(float4*)&Ps[(tq * 4 + i) * FBKV + kk];
                acc[i][0] += pv.x * vv[0].x + pv.y * vv[1].x + pv.z * vv[2].x + pv.w * vv[3].x;
                acc[i][1] += pv.x * vv[0].y + pv.y * vv[1].y + pv.z * vv[2].y + pv.w * vv[3].y;
                acc[i][2] += pv.x * vv[0].z + pv.y * vv[1].z + pv.z * vv[2].z + pv.w * vv[3].z;
                acc[i][3] += pv.x * vv[0].w + pv.y * vv[1].w + pv.z * vv[2].w + pv.w * vv[3].w;
            }
        }
        __syncthreads();
    }

    // Epilogue: normalize and store
#pragma unroll
    for (int i = 0; i < 4; i++) {
        float inv = 1.0f / l[i];
        float4 o;
        o.x = acc[i][0] * inv;
        o.y = acc[i][1] * inv;
        o.z = acc[i][2] * inv;
        o.w = acc[i][3] * inv;
        *(float4*)&O[base + (size_t)(q0 + tq * 4 + i) * EMBED + tk * 4] = o;
    }
}

// ---------------- host launch ----------------
extern "C" void kernel_launch(void* const* d_in, const int* in_sizes, int n_in,
                              void* d_out, int out_size)
{
    const float* x  = (const float*)d_in[0];
    const float* Wq = (const float*)d_in[1];
    const float* bq = (const float*)d_in[2];
    const float* Wk = (const float*)d_in[3];
    const float* bk = (const float*)d_in[4];
    const float* Wv = (const float*)d_in[5];
    const float* bv = (const float*)d_in[6];
    const float* Wo = (const float*)d_in[7];
    const float* bo = (const float*)d_in[8];
    float* out = (float*)d_out;

    float *qp, *kp, *vp, *cp;
    cudaGetSymbolAddress((void**)&qp, g_Q);
    cudaGetSymbolAddress((void**)&kp, g_K);
    cudaGetSymbolAddress((void**)&vp, g_V);
    cudaGetSymbolAddress((void**)&cp, g_ctx);

    const int smem_bytes = (3 * FBQ * FPAD + FBQ * FBKV) * (int)sizeof(float); // 68608
    cudaFuncSetAttribute(flash_attn_kernel,
                         cudaFuncAttributeMaxDynamicSharedMemorySize, smem_bytes);

    dim3 gemm_grid(EMBED / GBN, MTOT / GBM);   // (8, 64)
    dim3 gemm_block(256);

    // Q/K/V projections
    sgemm_bias_kernel<<<gemm_grid, gemm_block>>>(x, Wq, bq, qp, MTOT, EMBED, EMBED);
    sgemm_bias_kernel<<<gemm_grid, gemm_block>>>(x, Wk, bk, kp, MTOT, EMBED, EMBED);
    sgemm_bias_kernel<<<gemm_grid, gemm_block>>>(x, Wv, bv, vp, MTOT, EMBED, EMBED);

    // Attention
    dim3 fa_grid(SEQ / FBQ, NHEADS, BATCH);    // (32, 16, 4)
    flash_attn_kernel<<<fa_grid, 256, smem_bytes>>>(qp, kp, vp, cp);

    // Output projection
    sgemm_bias_kernel<<<gemm_grid, gemm_block>>>(cp, Wo, bo, out, MTOT, EMBED, EMBED);
}

// round 12
// speedup vs baseline: 1.3468x; 1.3468x over previous
#include <cuda_runtime.h>
#include <cuda_bf16.h>
#include <math.h>
#include <stdint.h>

#define EMBED   1024
#define NHEADS  16
#define HD      64
#define BATCH   4
#define SEQ     2048
#define MTOT    (BATCH * SEQ)   // 8192

// single dynamic-shared symbol shared by all kernels in this TU
extern __shared__ char dyn_smem[];

// ---------------- scratch (static __device__, no allocation) ----------------
__device__ float g_Q[(size_t)MTOT * EMBED];
__device__ float g_K[(size_t)MTOT * EMBED];
__device__ float g_V[(size_t)MTOT * EMBED];
__device__ float g_ctx[(size_t)MTOT * EMBED];

__device__ __nv_bfloat16 g_xh[(size_t)MTOT * EMBED];
__device__ __nv_bfloat16 g_xl[(size_t)MTOT * EMBED];
__device__ __nv_bfloat16 g_ch[(size_t)MTOT * EMBED];
__device__ __nv_bfloat16 g_cl[(size_t)MTOT * EMBED];

__device__ __nv_bfloat16 g_Wqh[(size_t)EMBED * EMBED];
__device__ __nv_bfloat16 g_Wql[(size_t)EMBED * EMBED];
__device__ __nv_bfloat16 g_Wkh[(size_t)EMBED * EMBED];
__device__ __nv_bfloat16 g_Wkl[(size_t)EMBED * EMBED];
__device__ __nv_bfloat16 g_Wvh[(size_t)EMBED * EMBED];
__device__ __nv_bfloat16 g_Wvl[(size_t)EMBED * EMBED];
__device__ __nv_bfloat16 g_Woh[(size_t)EMBED * EMBED];
__device__ __nv_bfloat16 g_Wol[(size_t)EMBED * EMBED];

// ======================= helpers ==============================
__device__ __forceinline__ uint32_t smem_u32(const void* p) {
    uint32_t a;
    asm("{ .reg .u64 t; cvta.to.shared.u64 t, %1; cvt.u32.u64 %0, t; }"
        : "=r"(a) : "l"(p));
    return a;
}
__device__ __forceinline__ void cp_async16(uint32_t dst, const void* src) {
    asm volatile("cp.async.cg.shared.global [%0], [%1], 16;"
                 :: "r"(dst), "l"(src) : "memory");
}
__device__ __forceinline__ void cp_commit() {
    asm volatile("cp.async.commit_group;" ::: "memory");
}
__device__ __forceinline__ void cp_wait0() {
    asm volatile("cp.async.wait_group 0;" ::: "memory");
}
__device__ __forceinline__ void ldmatrix_x4(uint32_t* r, uint32_t addr) {
    asm volatile("ldmatrix.sync.aligned.m8n8.x4.shared.b16 {%0,%1,%2,%3}, [%4];"
                 : "=r"(r[0]), "=r"(r[1]), "=r"(r[2]), "=r"(r[3]) : "r"(addr));
}
__device__ __forceinline__ void mma16816(float* d, const uint32_t* a,
                                         uint32_t b0, uint32_t b1) {
    asm volatile(
        "mma.sync.aligned.m16n8k16.row.col.f32.bf16.bf16.f32 "
        "{%0,%1,%2,%3}, {%4,%5,%6,%7}, {%8,%9}, {%0,%1,%2,%3};"
        : "+f"(d[0]), "+f"(d[1]), "+f"(d[2]), "+f"(d[3])
        : "r"(a[0]), "r"(a[1]), "r"(a[2]), "r"(a[3]), "r"(b0), "r"(b1));
}

// ======================= split / transpose kernels ==========================
__global__ __launch_bounds__(256) void split_kernel(
    const float* __restrict__ in, __nv_bfloat16* __restrict__ hi,
    __nv_bfloat16* __restrict__ lo, int n4)
{
    int i = blockIdx.x * 256 + threadIdx.x;
    if (i >= n4) return;
    float4 v = ((const float4*)in)[i];
    __nv_bfloat16 h0 = __float2bfloat16_rn(v.x);
    __nv_bfloat16 h1 = __float2bfloat16_rn(v.y);
    __nv_bfloat16 h2 = __float2bfloat16_rn(v.z);
    __nv_bfloat16 h3 = __float2bfloat16_rn(v.w);
    __nv_bfloat16 l0 = __float2bfloat16_rn(v.x - __bfloat162float(h0));
    __nv_bfloat16 l1 = __float2bfloat16_rn(v.y - __bfloat162float(h1));
    __nv_bfloat16 l2 = __float2bfloat16_rn(v.z - __bfloat162float(h2));
    __nv_bfloat16 l3 = __float2bfloat16_rn(v.w - __bfloat162float(h3));
    __nv_bfloat162* hp = (__nv_bfloat162*)hi;
    __nv_bfloat162* lp = (__nv_bfloat162*)lo;
    hp[2*i + 0] = __nv_bfloat162(h0, h1);
    hp[2*i + 1] = __nv_bfloat162(h2, h3);
    lp[2*i + 0] = __nv_bfloat162(l0, l1);
    lp[2*i + 1] = __nv_bfloat162(l2, l3);
}

// W[K=1024][N=1024] fp32 -> Wt_hi/lo[N][K] bf16 (transpose + split)
__global__ __launch_bounds__(256) void transpose_split_kernel(
    const float* __restrict__ W, __nv_bfloat16* __restrict__ hi,
    __nv_bfloat16* __restrict__ lo)
{
    __shared__ float t[32][33];
    int tx = threadIdx.x, ty = threadIdx.y;
    int n0 = blockIdx.x * 32;
    int k0 = blockIdx.y * 32;
#pragma unroll
    for (int j = 0; j < 4; j++)
        t[ty + j * 8][tx] = W[(size_t)(k0 + ty + j * 8) * EMBED + n0 + tx];
    __syncthreads();
#pragma unroll
    for (int j = 0; j < 4; j++) {
        float v = t[tx][ty + j * 8];
        __nv_bfloat16 h = __float2bfloat16_rn(v);
        __nv_bfloat16 l = __float2bfloat16_rn(v - __bfloat162float(h));
        size_t idx = (size_t)(n0 + ty + j * 8) * EMBED + k0 + tx;
        hi[idx] = h;
        lo[idx] = l;
    }
}

// ======================= mma.sync split GEMM =================================
// C[M=8192, N=1024] = (Ah+Al)[M,K] @ (Bh+Bl)^T[N,K] + bias, fp32 out.
// 3-term split: Ah*Bh + Al*Bh + Ah*Bl (Al*Bl ~ eps^2, dropped).
// CTA tile 128x128, K-chunk 64 bf16, double-buffered via cp.async.
// 8 warps: warp_m = wid&1 (2 x 64 rows), warp_n = wid>>1 (4 x 32 cols).
// Warp tile 64x32 = 4 m-tiles(16) x 4 n-tiles(8), mma m16n8k16.
#define TCM 128
#define TCN 128
#define TCK 64
#define NKCH (EMBED / TCK)        // 16
#define TILE_B  16384             // 128 rows x 64 bf16 (128B rows)
#define BUF_B   (4 * TILE_B)      // Ah, Al, Bh, Bl
#define GEMM_SMEM (2 * BUF_B)     // 131072

__global__ __launch_bounds__(256, 1)
void gemm_mma_kernel(
    const __nv_bfloat16* __restrict__ Ah, const __nv_bfloat16* __restrict__ Al,
    const __nv_bfloat16* __restrict__ Bh, const __nv_bfloat16* __restrict__ Bl,
    const float* __restrict__ bias, float* __restrict__ C)
{
    const uint32_t sb = smem_u32(dyn_smem);
    const int tid  = threadIdx.x;
    const int wid  = tid >> 5;
    const int lane = tid & 31;
    const int wm   = wid & 1;        // 0..1
    const int wn   = wid >> 1;       // 0..3
    const int brow = blockIdx.y * TCM;
    const int bcol = blockIdx.x * TCN;

    const __nv_bfloat16* srcs[4] = {
        Ah + (size_t)brow * EMBED, Al + (size_t)brow * EMBED,
        Bh + (size_t)bcol * EMBED, Bl + (size_t)bcol * EMBED };

    // ---- cp.async chunk loader: 4 tiles x 128 rows x 8 (16B units) ----
    const int ld_row  = tid >> 3;        // base row 0..31 (x4 iters)
    const int ld_unit = tid & 7;         // 16B unit in row
    auto load_chunk = [&](int c, int buf) {
        const uint32_t bufbase = sb + buf * BUF_B;
        const int k0 = c * TCK;
#pragma unroll
        for (int t = 0; t < 4; t++) {
#pragma unroll
            for (int it = 0; it < 4; it++) {
                const int row = ld_row + it * 32;
                const uint32_t dst = bufbase + t * TILE_B + row * 128 +
                                     ((ld_unit ^ (row & 7)) << 4);
                cp_async16(dst, srcs[t] + (size_t)row * EMBED + k0 + ld_unit * 8);
            }
        }
    };

    // ---- ldmatrix lane addressing ----
    const int quad = lane >> 3;
    const int l7   = lane & 7;
    const int rowA = ((quad & 1) << 3) + l7;   // + uex = quad>>1
    const int uexA = quad >> 1;
    const int rowB = ((quad >> 1) << 3) + l7;  // + uex = quad&1
    const int uexB = quad & 1;

    float acc[4][4][4];
#pragma unroll
    for (int mt = 0; mt < 4; mt++)
#pragma unroll
        for (int nt = 0; nt < 4; nt++)
#pragma unroll
            for (int j = 0; j < 4; j++) acc[mt][nt][j] = 0.0f;

    load_chunk(0, 0);
    cp_commit();
    cp_wait0();
    __syncthreads();

    for (int c = 0; c < NKCH; c++) {
        const int buf = c & 1;
        if (c + 1 < NKCH) { load_chunk(c + 1, buf ^ 1); cp_commit(); }

        const uint32_t TAh = sb + buf * BUF_B;
        const uint32_t TAl = TAh + TILE_B;
        const uint32_t TBh = TAh + 2 * TILE_B;
        const uint32_t TBl = TAh + 3 * TILE_B;

#pragma unroll
        for (int k16 = 0; k16 < 4; k16++) {
            uint32_t ah[4][4], al[4][4], bh[2][4], bl[2][4];
            const uint32_t aoff = ((uint32_t)(k16 * 2 + uexA) ^ l7) << 4;
            const uint32_t boff = ((uint32_t)(k16 * 2 + uexB) ^ l7) << 4;
#pragma unroll
            for (int mt = 0; mt < 4; mt++) {
                const uint32_t ro = (wm * 64 + mt * 16 + rowA) * 128;
                ldmatrix_x4(ah[mt], TAh + ro + aoff);
                ldmatrix_x4(al[mt], TAl + ro + aoff);
            }
#pragma unroll
            for (int g = 0; g < 2; g++) {
                const uint32_t ro = (wn * 32 + g * 16 + rowB) * 128;
                ldmatrix_x4(bh[g], TBh + ro + boff);
                ldmatrix_x4(bl[g], TBl + ro + boff);
            }
#pragma unroll
            for (int mt = 0; mt < 4; mt++) {
#pragma unroll
                for (int nt = 0; nt < 4; nt++) {
                    const int g = nt >> 1, ix = (nt & 1) * 2;
                    mma16816(acc[mt][nt], ah[mt], bh[g][ix], bh[g][ix + 1]);
                    mma16816(acc[mt][nt], al[mt], bh[g][ix], bh[g][ix + 1]);
                    mma16816(acc[mt][nt], ah[mt], bl[g][ix], bl[g][ix + 1]);
                }
            }
        }
        if (c + 1 < NKCH) cp_wait0();
        __syncthreads();
    }

    // ---- epilogue: fragment rows lane>>2 / +8, cols (lane&3)*2 ----
    const int gid = lane >> 2;
    const int tig = lane & 3;
#pragma unroll
    for (int mt = 0; mt < 4; mt++) {
        const int r0 = brow + wm * 64 + mt * 16 + gid;
#pragma unroll
        for (int nt = 0; nt < 4; nt++) {
            const int col = bcol + wn * 32 + nt * 8 + tig * 2;
            const float b0 = bias[col], b1 = bias[col + 1];
            float2 v0 = { acc[mt][nt][0] + b0, acc[mt][nt][1] + b1 };
            float2 v1 = { acc[mt][nt][2] + b0, acc[mt][nt][3] + b1 };
            *(float2*)&C[(size_t)r0 * EMBED + col] = v0;
            *(float2*)&C[(size_t)(r0 + 8) * EMBED + col] = v1;
        }
    }
}

// ---------------- Flash attention (fp32, online softmax) -------------------
#define FBQ  64
#define FBKV 64
#define FPAD 68

__global__ __launch_bounds__(256) void flash_attn_kernel(
    const float* __restrict__ Q, const float* __restrict__ K,
    const float* __restrict__ V, float* __restrict__ O)
{
    float* smem = (float*)dyn_smem;
    float* Qs = smem;
    float* Ks = Qs + FBQ * FPAD;
    float* Vs = Ks + FBKV * FPAD;
    float* Ps = Vs + FBKV * FPAD;

    const int tid = threadIdx.x;
    const int h   = blockIdx.y;
    const int b   = blockIdx.z;
    const int q0  = blockIdx.x * FBQ;
    const size_t base = (size_t)b * SEQ * EMBED + (size_t)h * HD;
    const float scale = 0.125f;

    for (int i = tid; i < FBQ * (HD / 4); i += 256) {
        int r = i >> 4;
        int c = (i & 15) * 4;
        float4 v = *(const float4*)&Q[base + (size_t)(q0 + r) * EMBED + c];
        v.x *= scale; v.y *= scale; v.z *= scale; v.w *= scale;
        *(float4*)&Qs[r * FPAD + c] = v;
    }

    const int tq = tid >> 4;
    const int tk = tid & 15;

    float m[4], l[4], acc[4][4];
#pragma unroll
    for (int i = 0; i < 4; i++) {
        m[i] = -1e30f; l[i] = 0.0f;
#pragma unroll
        for (int j = 0; j < 4; j++) acc[i][j] = 0.0f;
    }
    __syncthreads();

    for (int k0 = 0; k0 < SEQ; k0 += FBKV) {
        for (int i = tid; i < FBKV * (HD / 4); i += 256) {
            int r = i >> 4;
            int c = (i & 15) * 4;
            *(float4*)&Ks[r * FPAD + c] =
                *(const float4*)&K[base + (size_t)(k0 + r) * EMBED + c];
            *(float4*)&Vs[r * FPAD + c] =
                *(const float4*)&V[base + (size_t)(k0 + r) * EMBED + c];
        }
        __syncthreads();

        float s[4][4];
#pragma unroll
        for (int i = 0; i < 4; i++)
#pragma unroll
            for (int j = 0; j < 4; j++) s[i][j] = 0.0f;

        for (int d = 0; d < HD; d += 4) {
            float4 qv[4], kv[4];
#pragma unroll
            for (int i = 0; i < 4; i++)
                qv[i] = *(float4*)&Qs[(tq * 4 + i) * FPAD + d];
#pragma unroll
            for (int j = 0; j < 4; j++)
                kv[j] = *(float4*)&Ks[(tk * 4 + j) * FPAD + d];
#pragma unroll
            for (int i = 0; i < 4; i++)
#pragma unroll
                for (int j = 0; j < 4; j++)
                    s[i][j] += qv[i].x * kv[j].x + qv[i].y * kv[j].y
                             + qv[i].z * kv[j].z + qv[i].w * kv[j].w;
        }

#pragma unroll
        for (int i = 0; i < 4; i++) {
            float rmax = fmaxf(fmaxf(s[i][0], s[i][1]), fmaxf(s[i][2], s[i][3]));
#pragma unroll
            for (int off = 8; off > 0; off >>= 1)
                rmax = fmaxf(rmax, __shfl_xor_sync(0xffffffffu, rmax, off, 16));
            float mnew = fmaxf(m[i], rmax);
            float corr = __expf(m[i] - mnew);
            float4 p;
            p.x = __expf(s[i][0] - mnew);
            p.y = __expf(s[i][1] - mnew);
            p.z = __expf(s[i][2] - mnew);
            p.w = __expf(s[i][3] - mnew);
            float rsum = p.x + p.y + p.z + p.w;
#pragma unroll
            for (int off = 8; off > 0; off >>= 1)
                rsum += __shfl_xor_sync(0xffffffffu, rsum, off, 16);
            l[i] = l[i] * corr + rsum;
            m[i] = mnew;
            acc[i][0] *= corr; acc[i][1] *= corr;
            acc[i][2] *= corr; acc[i][3] *= corr;
            *(float4*)&Ps[(tq * 4 + i) * FBKV + tk * 4] = p;
        }
        __syncthreads();

        for (int kk = 0; kk < FBKV; kk += 4) {
            float4 vv[4];
#pragma unroll
            for (int jk = 0; jk < 4; jk++)
                vv[jk] = *(float4*)&Vs[(kk + jk) * FPAD + tk * 4];
#pragma unroll
            for (int i = 0; i < 4; i++) {
                float4 pv = *(float4*)&Ps[(tq * 4 + i) * FBKV + kk];
                acc[i][0] += pv.x * vv[0].x + pv.y * vv[1].x + pv.z * vv[2].x + pv.w * vv[3].x;
                acc[i][1] += pv.x * vv[0].y + pv.y * vv[1].y + pv.z * vv[2].y + pv.w * vv[3].y;
                acc[i][2] += pv.x * vv[0].z + pv.y * vv[1].z + pv.z * vv[2].z + pv.w * vv[3].z;
                acc[i][3] += pv.x * vv[0].w + pv.y * vv[1].w + pv.z * vv[2].w + pv.w * vv[3].w;
            }
        }
        __syncthreads();
    }

#pragma unroll
    for (int i = 0; i < 4; i++) {
        float inv = 1.0f / l[i];
        float4 o;
        o.x = acc[i][0] * inv;
        o.y = acc[i][1] * inv;
        o.z = acc[i][2] * inv;
        o.w = acc[i][3] * inv;
        *(float4*)&O[base + (size_t)(q0 + tq * 4 + i) * EMBED + tk * 4] = o;
    }
}

// ---------------- host launch ----------------
extern "C" void kernel_launch(void* const* d_in, const int* in_sizes, int n_in,
                              void* d_out, int out_size)
{
    const float* x  = (const float*)d_in[0];
    const float* Wq = (const float*)d_in[1];
    const float* bq = (const float*)d_in[2];
    const float* Wk = (const float*)d_in[3];
    const float* bk = (const float*)d_in[4];
    const float* Wv = (const float*)d_in[5];
    const float* bv = (const float*)d_in[6];
    const float* Wo = (const float*)d_in[7];
    const float* bo = (const float*)d_in[8];
    float* out = (float*)d_out;

    float *qp, *kp, *vp, *cp;
    cudaGetSymbolAddress((void**)&qp, g_Q);
    cudaGetSymbolAddress((void**)&kp, g_K);
    cudaGetSymbolAddress((void**)&vp, g_V);
    cudaGetSymbolAddress((void**)&cp, g_ctx);

    __nv_bfloat16 *xh, *xl, *ch, *cl;
    __nv_bfloat16 *wqh, *wql, *wkh, *wkl, *wvh, *wvl, *woh, *wol;
    cudaGetSymbolAddress((void**)&xh,  g_xh);
    cudaGetSymbolAddress((void**)&xl,  g_xl);
    cudaGetSymbolAddress((void**)&ch,  g_ch);
    cudaGetSymbolAddress((void**)&cl,  g_cl);
    cudaGetSymbolAddress((void**)&wqh, g_Wqh);
    cudaGetSymbolAddress((void**)&wql, g_Wql);
    cudaGetSymbolAddress((void**)&wkh, g_Wkh);
    cudaGetSymbolAddress((void**)&wkl, g_Wkl);
    cudaGetSymbolAddress((void**)&wvh, g_Wvh);
    cudaGetSymbolAddress((void**)&wvl, g_Wvl);
    cudaGetSymbolAddress((void**)&woh, g_Woh);
    cudaGetSymbolAddress((void**)&wol, g_Wol);

    cudaFuncSetAttribute(gemm_mma_kernel,
                         cudaFuncAttributeMaxDynamicSharedMemorySize, GEMM_SMEM);
    const int fa_smem = (3 * FBQ * FPAD + FBQ * FBKV) * (int)sizeof(float);
    cudaFuncSetAttribute(flash_attn_kernel,
                         cudaFuncAttributeMaxDynamicSharedMemorySize, fa_smem);

    // 1. split inputs to bf16 hi/lo
    const int n4 = MTOT * EMBED / 4;
    split_kernel<<<n4 / 256, 256>>>(x, xh, xl, n4);
    dim3 tg(EMBED / 32, EMBED / 32), tb(32, 8);
    transpose_split_kernel<<<tg, tb>>>(Wq, wqh, wql);
    transpose_split_kernel<<<tg, tb>>>(Wk, wkh, wkl);
    transpose_split_kernel<<<tg, tb>>>(Wv, wvh, wvl);
    transpose_split_kernel<<<tg, tb>>>(Wo, woh, wol);

    // 2. Q/K/V projections on tensor cores (mma.sync)
    dim3 gg(EMBED / TCN, MTOT / TCM);   // (8, 64)
    gemm_mma_kernel<<<gg, 256, GEMM_SMEM>>>(xh, xl, wqh, wql, bq, qp);
    gemm_mma_kernel<<<gg, 256, GEMM_SMEM>>>(xh, xl, wkh, wkl, bk, kp);
    gemm_mma_kernel<<<gg, 256, GEMM_SMEM>>>(xh, xl, wvh, wvl, bv, vp);

    // 3. attention
    dim3 fa_grid(SEQ / FBQ, NHEADS, BATCH);
    flash_attn_kernel<<<fa_grid, 256, fa_smem>>>(qp, kp, vp, cp);

    // 4. split context, output projection
    split_kernel<<<n4 / 256, 256>>>(cp, ch, cl, n4);
    gemm_mma_kernel<<<gg, 256, GEMM_SMEM>>>(ch, cl, woh, wol, bo, out);
}

// round 15
// speedup vs baseline: 4.8098x; 3.5713x over previous
#include <cuda_runtime.h>
#include <cuda_bf16.h>
#include <cuda_fp16.h>
#include <math.h>
#include <stdint.h>

#define EMBED   1024
#define NHEADS  16
#define HD      64
#define BATCH   4
#define SEQ     2048
#define MTOT    (BATCH * SEQ)   // 8192
#define BH      (BATCH * NHEADS) // 64

// single dynamic-shared symbol shared by all kernels in this TU
extern __shared__ char dyn_smem[];

// ---------------- scratch (static __device__, no allocation) ----------------
__device__ float g_Q[(size_t)MTOT * EMBED];
__device__ float g_K[(size_t)MTOT * EMBED];
__device__ float g_V[(size_t)MTOT * EMBED];
__device__ float g_ctx[(size_t)MTOT * EMBED];

__device__ __nv_bfloat16 g_xh[(size_t)MTOT * EMBED];
__device__ __nv_bfloat16 g_xl[(size_t)MTOT * EMBED];
__device__ __nv_bfloat16 g_ch[(size_t)MTOT * EMBED];
__device__ __nv_bfloat16 g_cl[(size_t)MTOT * EMBED];

__device__ __nv_bfloat16 g_Wqh[(size_t)EMBED * EMBED];
__device__ __nv_bfloat16 g_Wql[(size_t)EMBED * EMBED];
__device__ __nv_bfloat16 g_Wkh[(size_t)EMBED * EMBED];
__device__ __nv_bfloat16 g_Wkl[(size_t)EMBED * EMBED];
__device__ __nv_bfloat16 g_Wvh[(size_t)EMBED * EMBED];
__device__ __nv_bfloat16 g_Wvl[(size_t)EMBED * EMBED];
__device__ __nv_bfloat16 g_Woh[(size_t)EMBED * EMBED];
__device__ __nv_bfloat16 g_Wol[(size_t)EMBED * EMBED];

// fp16 attention operands, layout [b*H+h][s][64]
__device__ __half g_Qf[(size_t)BH * SEQ * HD];
__device__ __half g_Kf[(size_t)BH * SEQ * HD];
__device__ __half g_Vhh[(size_t)BH * SEQ * HD];
__device__ __half g_Vll[(size_t)BH * SEQ * HD];

// ======================= helpers ==============================
__device__ __forceinline__ uint32_t smem_u32(const void* p) {
    uint32_t a;
    asm("{ .reg .u64 t; cvta.to.shared.u64 t, %1; cvt.u32.u64 %0, t; }"
        : "=r"(a) : "l"(p));
    return a;
}
__device__ __forceinline__ void cp_async16(uint32_t dst, const void* src) {
    asm volatile("cp.async.cg.shared.global [%0], [%1], 16;"
                 :: "r"(dst), "l"(src) : "memory");
}
__device__ __forceinline__ void cp_commit() {
    asm volatile("cp.async.commit_group;" ::: "memory");
}
__device__ __forceinline__ void cp_wait0() {
    asm volatile("cp.async.wait_group 0;" ::: "memory");
}
__device__ __forceinline__ void ldmatrix_x4(uint32_t* r, uint32_t addr) {
    asm volatile("ldmatrix.sync.aligned.m8n8.x4.shared.b16 {%0,%1,%2,%3}, [%4];"
                 : "=r"(r[0]), "=r"(r[1]), "=r"(r[2]), "=r"(r[3]) : "r"(addr));
}
__device__ __forceinline__ void ldmatrix_x4_trans(uint32_t* r, uint32_t addr) {
    asm volatile("ldmatrix.sync.aligned.m8n8.x4.trans.shared.b16 {%0,%1,%2,%3}, [%4];"
                 : "=r"(r[0]), "=r"(r[1]), "=r"(r[2]), "=r"(r[3]) : "r"(addr));
}
__device__ __forceinline__ void mma16816(float* d, const uint32_t* a,
                                         uint32_t b0, uint32_t b1) {
    asm volatile(
        "mma.sync.aligned.m16n8k16.row.col.f32.bf16.bf16.f32 "
        "{%0,%1,%2,%3}, {%4,%5,%6,%7}, {%8,%9}, {%0,%1,%2,%3};"
        : "+f"(d[0]), "+f"(d[1]), "+f"(d[2]), "+f"(d[3])
        : "r"(a[0]), "r"(a[1]), "r"(a[2]), "r"(a[3]), "r"(b0), "r"(b1));
}
__device__ __forceinline__ void mma16816h(float* d, const uint32_t* a,
                                          uint32_t b0, uint32_t b1) {
    asm volatile(
        "mma.sync.aligned.m16n8k16.row.col.f32.f16.f16.f32 "
        "{%0,%1,%2,%3}, {%4,%5,%6,%7}, {%8,%9}, {%0,%1,%2,%3};"
        : "+f"(d[0]), "+f"(d[1]), "+f"(d[2]), "+f"(d[3])
        : "r"(a[0]), "r"(a[1]), "r"(a[2]), "r"(a[3]), "r"(b0), "r"(b1));
}
__device__ __forceinline__ uint32_t packh2(float lo, float hi) {
    __half2 h = __floats2half2_rn(lo, hi);
    return *(uint32_t*)&h;
}

// ======================= split / transpose kernels ==========================
__global__ __launch_bounds__(256) void split_kernel(
    const float* __restrict__ in, __nv_bfloat16* __restrict__ hi,
    __nv_bfloat16* __restrict__ lo, int n4)
{
    int i = blockIdx.x * 256 + threadIdx.x;
    if (i >= n4) return;
    float4 v = ((const float4*)in)[i];
    __nv_bfloat16 h0 = __float2bfloat16_rn(v.x);
    __nv_bfloat16 h1 = __float2bfloat16_rn(v.y);
    __nv_bfloat16 h2 = __float2bfloat16_rn(v.z);
    __nv_bfloat16 h3 = __float2bfloat16_rn(v.w);
    __nv_bfloat16 l0 = __float2bfloat16_rn(v.x - __bfloat162float(h0));
    __nv_bfloat16 l1 = __float2bfloat16_rn(v.y - __bfloat162float(h1));
    __nv_bfloat16 l2 = __float2bfloat16_rn(v.z - __bfloat162float(h2));
    __nv_bfloat16 l3 = __float2bfloat16_rn(v.w - __bfloat162float(h3));
    __nv_bfloat162* hp = (__nv_bfloat162*)hi;
    __nv_bfloat162* lp = (__nv_bfloat162*)lo;
    hp[2*i + 0] = __nv_bfloat162(h0, h1);
    hp[2*i + 1] = __nv_bfloat162(h2, h3);
    lp[2*i + 0] = __nv_bfloat162(l0, l1);
    lp[2*i + 1] = __nv_bfloat162(l2, l3);
}

// W[K=1024][N=1024] fp32 -> Wt_hi/lo[N][K] bf16 (transpose + split)
__global__ __launch_bounds__(256) void transpose_split_kernel(
    const float* __restrict__ W, __nv_bfloat16* __restrict__ hi,
    __nv_bfloat16* __restrict__ lo)
{
    __shared__ float t[32][33];
    int tx = threadIdx.x, ty = threadIdx.y;
    int n0 = blockIdx.x * 32;
    int k0 = blockIdx.y * 32;
#pragma unroll
    for (int j = 0; j < 4; j++)
        t[ty + j * 8][tx] = W[(size_t)(k0 + ty + j * 8) * EMBED + n0 + tx];
    __syncthreads();
#pragma unroll
    for (int j = 0; j < 4; j++) {
        float v = t[tx][ty + j * 8];
        __nv_bfloat16 h = __float2bfloat16_rn(v);
        __nv_bfloat16 l = __float2bfloat16_rn(v - __bfloat162float(h));
        size_t idx = (size_t)(n0 + ty + j * 8) * EMBED + k0 + tx;
        hi[idx] = h;
        lo[idx] = l;
    }
}

// [b][s][e] fp32 -> [bh][s][64] fp16 (hi, optional lo residual), scaled
__global__ __launch_bounds__(256) void attn_split_kernel(
    const float* __restrict__ src, __half* __restrict__ hi,
    __half* __restrict__ lo, float scale)
{
    const int bh = blockIdx.y, s0 = blockIdx.x * 32;
    const int r = threadIdx.x >> 3, u = threadIdx.x & 7;
    const int b = bh >> 4, h = bh & 15;
    const float* p = src + ((size_t)b * SEQ + s0 + r) * EMBED + h * HD + u * 8;
    float v[8];
    *(float4*)&v[0] = ((const float4*)p)[0];
    *(float4*)&v[4] = ((const float4*)p)[1];
    __half hh[8], ll[8];
#pragma unroll
    for (int j = 0; j < 8; j++) {
        float sv = v[j] * scale;
        hh[j] = __float2half_rn(sv);
        ll[j] = __float2half_rn(sv - __half2float(hh[j]));
    }
    const size_t d = ((size_t)bh * SEQ + s0 + r) * HD + u * 8;
    *(uint4*)&hi[d] = *(uint4*)hh;
    if (lo) *(uint4*)&lo[d] = *(uint4*)ll;
}

// ======================= mma.sync split GEMM (unchanged) =====================
#define TCM 128
#define TCN 128
#define TCK 64
#define NKCH (EMBED / TCK)        // 16
#define TILE_B  16384             // 128 rows x 64 bf16 (128B rows)
#define BUF_B   (4 * TILE_B)      // Ah, Al, Bh, Bl
#define GEMM_SMEM (2 * BUF_B)     // 131072

__global__ __launch_bounds__(256, 1)
void gemm_mma_kernel(
    const __nv_bfloat16* __restrict__ Ah, const __nv_bfloat16* __restrict__ Al,
    const __nv_bfloat16* __restrict__ Bh, const __nv_bfloat16* __restrict__ Bl,
    const float* __restrict__ bias, float* __restrict__ C)
{
    const uint32_t sb = smem_u32(dyn_smem);
    const int tid  = threadIdx.x;
    const int wid  = tid >> 5;
    const int lane = tid & 31;
    const int wm   = wid & 1;
    const int wn   = wid >> 1;
    const int brow = blockIdx.y * TCM;
    const int bcol = blockIdx.x * TCN;

    const __nv_bfloat16* srcs[4] = {
        Ah + (size_t)brow * EMBED, Al + (size_t)brow * EMBED,
        Bh + (size_t)bcol * EMBED, Bl + (size_t)bcol * EMBED };

    const int ld_row  = tid >> 3;
    const int ld_unit = tid & 7;
    auto load_chunk = [&](int c, int buf) {
        const uint32_t bufbase = sb + buf * BUF_B;
        const int k0 = c * TCK;
#pragma unroll
        for (int t = 0; t < 4; t++) {
#pragma unroll
            for (int it = 0; it < 4; it++) {
                const int row = ld_row + it * 32;
                const uint32_t dst = bufbase + t * TILE_B + row * 128 +
                                     ((ld_unit ^ (row & 7)) << 4);
                cp_async16(dst, srcs[t] + (size_t)row * EMBED + k0 + ld_unit * 8);
            }
        }
    };

    const int quad = lane >> 3;
    const int l7   = lane & 7;
    const int rowA = ((quad & 1) << 3) + l7;
    const int uexA = quad >> 1;
    const int rowB = ((quad >> 1) << 3) + l7;
    const int uexB = quad & 1;

    float acc[4][4][4];
#pragma unroll
    for (int mt = 0; mt < 4; mt++)
#pragma unroll
        for (int nt = 0; nt < 4; nt++)
#pragma unroll
            for (int j = 0; j < 4; j++) acc[mt][nt][j] = 0.0f;

    load_chunk(0, 0);
    cp_commit();
    cp_wait0();
    __syncthreads();

    for (int c = 0; c < NKCH; c++) {
        const int buf = c & 1;
        if (c + 1 < NKCH) { load_chunk(c + 1, buf ^ 1); cp_commit(); }

        const uint32_t TAh = sb + buf * BUF_B;
        const uint32_t TAl = TAh + TILE_B;
        const uint32_t TBh = TAh + 2 * TILE_B;
        const uint32_t TBl = TAh + 3 * TILE_B;

#pragma unroll
        for (int k16 = 0; k16 < 4; k16++) {
            uint32_t ah[4][4], al[4][4], bh[2][4], bl[2][4];
            const uint32_t aoff = ((uint32_t)(k16 * 2 + uexA) ^ l7) << 4;
            const uint32_t boff = ((uint32_t)(k16 * 2 + uexB) ^ l7) << 4;
#pragma unroll
            for (int mt = 0; mt < 4; mt++) {
                const uint32_t ro = (wm * 64 + mt * 16 + rowA) * 128;
                ldmatrix_x4(ah[mt], TAh + ro + aoff);
                ldmatrix_x4(al[mt], TAl + ro + aoff);
            }
#pragma unroll
            for (int g = 0; g < 2; g++) {
                const uint32_t ro = (wn * 32 + g * 16 + rowB) * 128;
                ldmatrix_x4(bh[g], TBh + ro + boff);
                ldmatrix_x4(bl[g], TBl + ro + boff);
            }
#pragma unroll
            for (int mt = 0; mt < 4; mt++) {
#pragma unroll
                for (int nt = 0; nt < 4; nt++) {
                    const int g = nt >> 1, ix = (nt & 1) * 2;
                    mma16816(acc[mt][nt], ah[mt], bh[g][ix], bh[g][ix + 1]);
                    mma16816(acc[mt][nt], al[mt], bh[g][ix], bh[g][ix + 1]);
                    mma16816(acc[mt][nt], ah[mt], bl[g][ix], bl[g][ix + 1]);
                }
            }
        }
        if (c + 1 < NKCH) cp_wait0();
        __syncthreads();
    }

    const int gid = lane >> 2;
    const int tig = lane & 3;
#pragma unroll
    for (int mt = 0; mt < 4; mt++) {
        const int r0 = brow + wm * 64 + mt * 16 + gid;
#pragma unroll
        for (int nt = 0; nt < 4; nt++) {
            const int col = bcol + wn * 32 + nt * 8 + tig * 2;
            const float b0 = bias[col], b1 = bias[col + 1];
            float2 v0 = { acc[mt][nt][0] + b0, acc[mt][nt][1] + b1 };
            float2 v1 = { acc[mt][nt][2] + b0, acc[mt][nt][3] + b1 };
            *(float2*)&C[(size_t)r0 * EMBED + col] = v0;
            *(float2*)&C[(size_t)(r0 + 8) * EMBED + col] = v1;
        }
    }
}

// ================= fp16 mma flash attention ==================================
// CTA: 128 q rows x one (b,h). 8 warps, each owns 16 q rows.
// QK: 1-term fp16. PV: 3-term (PhVh + PlVh + PhVl), P split in registers.
// smem: Qf[128][64]f16 (16KB) + 2 bufs x (Kf + Vh + Vl)[64][64]f16 (24KB each).
#define FQ 128
#define FA_BUF 24576
#define FA_SMEM (16384 + 2 * FA_BUF)   // 65536
#define NKVT (SEQ / 64)                // 32

__global__ __launch_bounds__(256, 1) void flash_mma_kernel(
    const __half* __restrict__ Qf, const __half* __restrict__ Kf,
    const __half* __restrict__ Vh, const __half* __restrict__ Vl,
    float* __restrict__ O)
{
    const uint32_t sb = smem_u32(dyn_smem);
    const int tid = threadIdx.x, wid = tid >> 5, lane = tid & 31;
    const int bh = blockIdx.y;
    const int q0 = blockIdx.x * FQ;
    const size_t qoff  = ((size_t)bh * SEQ + q0) * HD;
    const size_t kvoff = (size_t)bh * SEQ * HD;

    // load Q tile (persistent)
    {
        const int u = tid & 7, r0 = tid >> 3;
#pragma unroll
        for (int it = 0; it < 4; it++) {
            const int row = r0 + it * 32;
            cp_async16(sb + row * 128 + (((uint32_t)(u ^ (row & 7))) << 4),
                       Qf + qoff + (size_t)row * HD + u * 8);
        }
    }
    auto load_kv = [&](int t, int buf) {
        const int u = tid & 7, r0 = tid >> 3;
        const size_t off = kvoff + (size_t)t * 64 * HD;
        const uint32_t bb = sb + 16384 + buf * FA_BUF;
        const __half* srcs[3] = { Kf + off, Vh + off, Vl + off };
#pragma unroll
        for (int ts = 0; ts < 3; ts++)
#pragma unroll
            for (int it = 0; it < 2; it++) {
                const int row = r0 + it * 32;
                cp_async16(bb + ts * 8192 + row * 128 +
                           (((uint32_t)(u ^ (row & 7))) << 4),
                           srcs[ts] + (size_t)row * HD + u * 8);
            }
    };
    load_kv(0, 0);
    cp_commit();
    cp_wait0();
    __syncthreads();

    const int quad = lane >> 3, l7 = lane & 7;
    const int rowA = ((quad & 1) << 3) + l7, uexA = quad >> 1;
    const int rowB = ((quad >> 1) << 3) + l7, uexB = quad & 1;
    const int vrow = (((lane >> 3) & 1) << 3) + l7, vuex = lane >> 4;
    const int gid = lane >> 2, tig = lane & 3;

    float m0 = -1e30f, m1 = -1e30f, l0 = 0.0f, l1 = 0.0f;
    float o[8][4];
#pragma unroll
    for (int dt = 0; dt < 8; dt++)
#pragma unroll
        for (int j = 0; j < 4; j++) o[dt][j] = 0.0f;

    for (int t = 0; t < NKVT; t++) {
        const int buf = t & 1;
        if (t + 1 < NKVT) { load_kv(t + 1, buf ^ 1); cp_commit(); }
        const uint32_t kb = sb + 16384 + buf * FA_BUF;

        // ---- scores S = Q @ K^T ----
        float s[8][4];
#pragma unroll
        for (int nt = 0; nt < 8; nt++)
#pragma unroll
            for (int j = 0; j < 4; j++) s[nt][j] = 0.0f;

#pragma unroll
        for (int kc = 0; kc < 4; kc++) {
            uint32_t a4[4];
            ldmatrix_x4(a4, sb + (wid * 16 + rowA) * 128 +
                        (((uint32_t)((kc * 2 + uexA) ^ l7)) << 4));
#pragma unroll
            for (int g = 0; g < 4; g++) {
                uint32_t k4[4];
                ldmatrix_x4(k4, kb + (g * 16 + rowB) * 128 +
                            (((uint32_t)((kc * 2 + uexB) ^ l7)) << 4));
                mma16816h(s[2 * g],     a4, k4[0], k4[1]);
                mma16816h(s[2 * g + 1], a4, k4[2], k4[3]);
            }
        }

        // ---- online softmax (rows gid, gid+8; quad-replicated) ----
        float M0 = -1e30f, M1 = -1e30f;
#pragma unroll
        for (int nt = 0; nt < 8; nt++) {
            M0 = fmaxf(M0, fmaxf(s[nt][0], s[nt][1]));
            M1 = fmaxf(M1, fmaxf(s[nt][2], s[nt][3]));
        }
        M0 = fmaxf(M0, __shfl_xor_sync(0xffffffffu, M0, 1));
        M0 = fmaxf(M0, __shfl_xor_sync(0xffffffffu, M0, 2));
        M1 = fmaxf(M1, __shfl_xor_sync(0xffffffffu, M1, 1));
        M1 = fmaxf(M1, __shfl_xor_sync(0xffffffffu, M1, 2));
        const float mn0 = fmaxf(m0, M0), mn1 = fmaxf(m1, M1);
        const float c0 = __expf(m0 - mn0), c1 = __expf(m1 - mn1);
        m0 = mn0; m1 = mn1;
        float sum0 = 0.0f, sum1 = 0.0f;
#pragma unroll
        for (int nt = 0; nt < 8; nt++) {
            s[nt][0] = __expf(s[nt][0] - mn0);
            s[nt][1] = __expf(s[nt][1] - mn0);
            s[nt][2] = __expf(s[nt][2] - mn1);
            s[nt][3] = __expf(s[nt][3] - mn1);
            sum0 += s[nt][0] + s[nt][1];
            sum1 += s[nt][2] + s[nt][3];
        }
        sum0 += __shfl_xor_sync(0xffffffffu, sum0, 1);
        sum0 += __shfl_xor_sync(0xffffffffu, sum0, 2);
        sum1 += __shfl_xor_sync(0xffffffffu, sum1, 1);
        sum1 += __shfl_xor_sync(0xffffffffu, sum1, 2);
        l0 = l0 * c0 + sum0;
        l1 = l1 * c1 + sum1;
#pragma unroll
        for (int dt = 0; dt < 8; dt++) {
            o[dt][0] *= c0; o[dt][1] *= c0;
            o[dt][2] *= c1; o[dt][3] *= c1;
        }

        // ---- O += P @ V (P split hi/lo in registers, V split in smem) ----
#pragma unroll
        for (int kc = 0; kc < 4; kc++) {
            uint32_t ph[4], pl[4];
#pragma unroll
            for (int half2i = 0; half2i < 4; half2i++) {
                const int nt = 2 * kc + (half2i >> 1);
                const int j0 = (half2i & 1) * 2;
                const float p0 = s[nt][j0], p1 = s[nt][j0 + 1];
                const __half h0 = __float2half_rn(p0);
                const __half h1 = __float2half_rn(p1);
                ph[half2i] = packh2(__half2float(h0) * 0.0f + p0 - (p0 - __half2float(h0)),
                                    p1 - (p1 - __half2float(h1)));
                // simpler: ph = pack(h0,h1); pl = residuals
                __half2 hp; hp.x = h0; hp.y = h1;
                ph[half2i] = *(uint32_t*)&hp;
                pl[half2i] = packh2(p0 - __half2float(h0), p1 - __half2float(h1));
            }
#pragma unroll
            for (int g2 = 0; g2 < 4; g2++) {
                uint32_t vh4[4], vl4[4];
                const uint32_t vro = kb + 8192 + (kc * 16 + vrow) * 128 +
                                     (((uint32_t)((g2 * 2 + vuex) ^ l7)) << 4);
                ldmatrix_x4_trans(vh4, vro);
                ldmatrix_x4_trans(vl4, vro + 8192);
                mma16816h(o[2 * g2],     ph, vh4[0], vh4[1]);
                mma16816h(o[2 * g2],     pl, vh4[0], vh4[1]);
                mma16816h(o[2 * g2],     ph, vl4[0], vl4[1]);
                mma16816h(o[2 * g2 + 1], ph, vh4[2], vh4[3]);
                mma16816h(o[2 * g2 + 1], pl, vh4[2], vh4[3]);
                mma16816h(o[2 * g2 + 1], ph, vl4[2], vl4[3]);
            }
        }
        if (t + 1 < NKVT) cp_wait0();
        __syncthreads();
    }

    // ---- epilogue ----
    const float i0 = 1.0f / l0, i1 = 1.0f / l1;
    const int b = bh >> 4, h = bh & 15;
    const int r0 = q0 + wid * 16 + gid;
    float* out0 = O + ((size_t)b * SEQ + r0) * EMBED + h * HD;
#pragma unroll
    for (int dt = 0; dt < 8; dt++) {
        const int col = dt * 8 + tig * 2;
        float2 v0 = { o[dt][0] * i0, o[dt][1] * i0 };
        float2 v1 = { o[dt][2] * i1, o[dt][3] * i1 };
        *(float2*)&out0[col] = v0;
        *(float2*)&out0[8 * EMBED + col] = v1;
    }
}

// ---------------- host launch ----------------
extern "C" void kernel_launch(void* const* d_in, const int* in_sizes, int n_in,
                              void* d_out, int out_size)
{
    const float* x  = (const float*)d_in[0];
    const float* Wq = (const float*)d_in[1];
    const float* bq = (const float*)d_in[2];
    const float* Wk = (const float*)d_in[3];
    const float* bk = (const float*)d_in[4];
    const float* Wv = (const float*)d_in[5];
    const float* bv = (const float*)d_in[6];
    const float* Wo = (const float*)d_in[7];
    const float* bo = (const float*)d_in[8];
    float* out = (float*)d_out;

    float *qp, *kp, *vp, *cp;
    cudaGetSymbolAddress((void**)&qp, g_Q);
    cudaGetSymbolAddress((void**)&kp, g_K);
    cudaGetSymbolAddress((void**)&vp, g_V);
    cudaGetSymbolAddress((void**)&cp, g_ctx);

    __nv_bfloat16 *xh, *xl, *ch, *cl;
    __nv_bfloat16 *wqh, *wql, *wkh, *wkl, *wvh, *wvl, *woh, *wol;
    cudaGetSymbolAddress((void**)&xh,  g_xh);
    cudaGetSymbolAddress((void**)&xl,  g_xl);
    cudaGetSymbolAddress((void**)&ch,  g_ch);
    cudaGetSymbolAddress((void**)&cl,  g_cl);
    cudaGetSymbolAddress((void**)&wqh, g_Wqh);
    cudaGetSymbolAddress((void**)&wql, g_Wql);
    cudaGetSymbolAddress((void**)&wkh, g_Wkh);
    cudaGetSymbolAddress((void**)&wkl, g_Wkl);
    cudaGetSymbolAddress((void**)&wvh, g_Wvh);
    cudaGetSymbolAddress((void**)&wvl, g_Wvl);
    cudaGetSymbolAddress((void**)&woh, g_Woh);
    cudaGetSymbolAddress((void**)&wol, g_Wol);

    __half *qf, *kf, *vhh, *vll;
    cudaGetSymbolAddress((void**)&qf,  g_Qf);
    cudaGetSymbolAddress((void**)&kf,  g_Kf);
    cudaGetSymbolAddress((void**)&vhh, g_Vhh);
    cudaGetSymbolAddress((void**)&vll, g_Vll);

    cudaFuncSetAttribute(gemm_mma_kernel,
                         cudaFuncAttributeMaxDynamicSharedMemorySize, GEMM_SMEM);
    cudaFuncSetAttribute(flash_mma_kernel,
                         cudaFuncAttributeMaxDynamicSharedMemorySize, FA_SMEM);

    // 1. split inputs to bf16 hi/lo
    const int n4 = MTOT * EMBED / 4;
    split_kernel<<<n4 / 256, 256>>>(x, xh, xl, n4);
    dim3 tg(EMBED / 32, EMBED / 32), tb(32, 8);
    transpose_split_kernel<<<tg, tb>>>(Wq, wqh, wql);
    transpose_split_kernel<<<tg, tb>>>(Wk, wkh, wkl);
    transpose_split_kernel<<<tg, tb>>>(Wv, wvh, wvl);
    transpose_split_kernel<<<tg, tb>>>(Wo, woh, wol);

    // 2. Q/K/V projections on tensor cores (mma.sync)
    dim3 gg(EMBED / TCN, MTOT / TCM);   // (8, 64)
    gemm_mma_kernel<<<gg, 256, GEMM_SMEM>>>(xh, xl, wqh, wql, bq, qp);
    gemm_mma_kernel<<<gg, 256, GEMM_SMEM>>>(xh, xl, wkh, wkl, bk, kp);
    gemm_mma_kernel<<<gg, 256, GEMM_SMEM>>>(xh, xl, wvh, wvl, bv, vp);

    // 3. fp16 attention operands ([bh][s][64] layout)
    dim3 ag(SEQ / 32, BH);
    attn_split_kernel<<<ag, 256>>>(qp, qf, nullptr, 0.125f);
    attn_split_kernel<<<ag, 256>>>(kp, kf, nullptr, 1.0f);
    attn_split_kernel<<<ag, 256>>>(vp, vhh, vll, 1.0f);

    // 4. flash attention on fp16 tensor cores
    dim3 fg(SEQ / FQ, BH);              // (16, 64)
    flash_mma_kernel<<<fg, 256, FA_SMEM>>>(qf, kf, vhh, vll, cp);

    // 5. split context, output projection
    split_kernel<<<n4 / 256, 256>>>(cp, ch, cl, n4);
    gemm_mma_kernel<<<gg, 256, GEMM_SMEM>>>(ch, cl, woh, wol, bo, out);
}

// round 16
// speedup vs baseline: 5.8153x; 1.2090x over previous
#include <cuda_runtime.h>
#include <cuda_bf16.h>
#include <cuda_fp16.h>
#include <math.h>
#include <stdint.h>

#define EMBED   1024
#define NHEADS  16
#define HD      64
#define BATCH   4
#define SEQ     2048
#define MTOT    (BATCH * SEQ)   // 8192
#define BH      (BATCH * NHEADS) // 64

// single dynamic-shared symbol shared by all kernels in this TU
extern __shared__ char dyn_smem[];

// ---------------- scratch (static __device__, no allocation) ----------------
__device__ __nv_bfloat16 g_xh[(size_t)MTOT * EMBED];
__device__ __nv_bfloat16 g_xl[(size_t)MTOT * EMBED];
__device__ __half        g_xf[(size_t)MTOT * EMBED];
__device__ __nv_bfloat16 g_ch[(size_t)MTOT * EMBED];
__device__ __nv_bfloat16 g_cl[(size_t)MTOT * EMBED];

__device__ __half        g_Wqt[(size_t)EMBED * EMBED];
__device__ __half        g_Wkt[(size_t)EMBED * EMBED];
__device__ __nv_bfloat16 g_Wvh[(size_t)EMBED * EMBED];
__device__ __nv_bfloat16 g_Wvl[(size_t)EMBED * EMBED];
__device__ __nv_bfloat16 g_Woh[(size_t)EMBED * EMBED];
__device__ __nv_bfloat16 g_Wol[(size_t)EMBED * EMBED];

// fp16 attention operands, layout [b*H+h][s][64]
__device__ __half g_Qf[(size_t)BH * SEQ * HD];
__device__ __half g_Kf[(size_t)BH * SEQ * HD];
__device__ __half g_Vhh[(size_t)BH * SEQ * HD];
__device__ __half g_Vll[(size_t)BH * SEQ * HD];

// ======================= helpers ==============================
__device__ __forceinline__ uint32_t smem_u32(const void* p) {
    uint32_t a;
    asm("{ .reg .u64 t; cvta.to.shared.u64 t, %1; cvt.u32.u64 %0, t; }"
        : "=r"(a) : "l"(p));
    return a;
}
__device__ __forceinline__ void cp_async16(uint32_t dst, const void* src) {
    asm volatile("cp.async.cg.shared.global [%0], [%1], 16;"
                 :: "r"(dst), "l"(src) : "memory");
}
__device__ __forceinline__ void cp_commit() {
    asm volatile("cp.async.commit_group;" ::: "memory");
}
__device__ __forceinline__ void cp_wait0() {
    asm volatile("cp.async.wait_group 0;" ::: "memory");
}
__device__ __forceinline__ void ldmatrix_x4(uint32_t* r, uint32_t addr) {
    asm volatile("ldmatrix.sync.aligned.m8n8.x4.shared.b16 {%0,%1,%2,%3}, [%4];"
                 : "=r"(r[0]), "=r"(r[1]), "=r"(r[2]), "=r"(r[3]) : "r"(addr));
}
__device__ __forceinline__ void ldmatrix_x4_trans(uint32_t* r, uint32_t addr) {
    asm volatile("ldmatrix.sync.aligned.m8n8.x4.trans.shared.b16 {%0,%1,%2,%3}, [%4];"
                 : "=r"(r[0]), "=r"(r[1]), "=r"(r[2]), "=r"(r[3]) : "r"(addr));
}
__device__ __forceinline__ void mma16816(float* d, const uint32_t* a,
                                         uint32_t b0, uint32_t b1) {
    asm volatile(
        "mma.sync.aligned.m16n8k16.row.col.f32.bf16.bf16.f32 "
        "{%0,%1,%2,%3}, {%4,%5,%6,%7}, {%8,%9}, {%0,%1,%2,%3};"
        : "+f"(d[0]), "+f"(d[1]), "+f"(d[2]), "+f"(d[3])
        : "r"(a[0]), "r"(a[1]), "r"(a[2]), "r"(a[3]), "r"(b0), "r"(b1));
}
__device__ __forceinline__ void mma16816h(float* d, const uint32_t* a,
                                          uint32_t b0, uint32_t b1) {
    asm volatile(
        "mma.sync.aligned.m16n8k16.row.col.f32.f16.f16.f32 "
        "{%0,%1,%2,%3}, {%4,%5,%6,%7}, {%8,%9}, {%0,%1,%2,%3};"
        : "+f"(d[0]), "+f"(d[1]), "+f"(d[2]), "+f"(d[3])
        : "r"(a[0]), "r"(a[1]), "r"(a[2]), "r"(a[3]), "r"(b0), "r"(b1));
}
__device__ __forceinline__ uint32_t packh2(float lo, float hi) {
    __half2 h = __floats2half2_rn(lo, hi);
    return *(uint32_t*)&h;
}

// ======================= split / transpose kernels ==========================
// x fp32 -> bf16 hi/lo (for V gemm) + fp16 (for Q/K gemms)
__global__ __launch_bounds__(256) void split_x_kernel(
    const float* __restrict__ in, __nv_bfloat16* __restrict__ hi,
    __nv_bfloat16* __restrict__ lo, __half* __restrict__ f16, int n4)
{
    int i = blockIdx.x * 256 + threadIdx.x;
    if (i >= n4) return;
    float4 v = ((const float4*)in)[i];
    __nv_bfloat16 h0 = __float2bfloat16_rn(v.x);
    __nv_bfloat16 h1 = __float2bfloat16_rn(v.y);
    __nv_bfloat16 h2 = __float2bfloat16_rn(v.z);
    __nv_bfloat16 h3 = __float2bfloat16_rn(v.w);
    __nv_bfloat16 l0 = __float2bfloat16_rn(v.x - __bfloat162float(h0));
    __nv_bfloat16 l1 = __float2bfloat16_rn(v.y - __bfloat162float(h1));
    __nv_bfloat16 l2 = __float2bfloat16_rn(v.z - __bfloat162float(h2));
    __nv_bfloat16 l3 = __float2bfloat16_rn(v.w - __bfloat162float(h3));
    __nv_bfloat162* hp = (__nv_bfloat162*)hi;
    __nv_bfloat162* lp = (__nv_bfloat162*)lo;
    hp[2*i + 0] = __nv_bfloat162(h0, h1);
    hp[2*i + 1] = __nv_bfloat162(h2, h3);
    lp[2*i + 0] = __nv_bfloat162(l0, l1);
    lp[2*i + 1] = __nv_bfloat162(l2, l3);
    __half2* fp = (__half2*)f16;
    fp[2*i + 0] = __floats2half2_rn(v.x, v.y);
    fp[2*i + 1] = __floats2half2_rn(v.z, v.w);
}

// W[K][N] fp32 -> Wt_hi/lo[N][K] bf16 (transpose + split)
__global__ __launch_bounds__(256) void transpose_split_kernel(
    const float* __restrict__ W, __nv_bfloat16* __restrict__ hi,
    __nv_bfloat16* __restrict__ lo)
{
    __shared__ float t[32][33];
    int tx = threadIdx.x, ty = threadIdx.y;
    int n0 = blockIdx.x * 32;
    int k0 = blockIdx.y * 32;
#pragma unroll
    for (int j = 0; j < 4; j++)
        t[ty + j * 8][tx] = W[(size_t)(k0 + ty + j * 8) * EMBED + n0 + tx];
    __syncthreads();
#pragma unroll
    for (int j = 0; j < 4; j++) {
        float v = t[tx][ty + j * 8];
        __nv_bfloat16 h = __float2bfloat16_rn(v);
        __nv_bfloat16 l = __float2bfloat16_rn(v - __bfloat162float(h));
        size_t idx = (size_t)(n0 + ty + j * 8) * EMBED + k0 + tx;
        hi[idx] = h;
        lo[idx] = l;
    }
}

// W[K][N] fp32 -> Wt[N][K] fp16 (transpose, single precision level)
__global__ __launch_bounds__(256) void transpose_f16_kernel(
    const float* __restrict__ W, __half* __restrict__ out)
{
    __shared__ float t[32][33];
    int tx = threadIdx.x, ty = threadIdx.y;
    int n0 = blockIdx.x * 32;
    int k0 = blockIdx.y * 32;
#pragma unroll
    for (int j = 0; j < 4; j++)
        t[ty + j * 8][tx] = W[(size_t)(k0 + ty + j * 8) * EMBED + n0 + tx];
    __syncthreads();
#pragma unroll
    for (int j = 0; j < 4; j++) {
        float v = t[tx][ty + j * 8];
        out[(size_t)(n0 + ty + j * 8) * EMBED + k0 + tx] = __float2half_rn(v);
    }
}

// ======================= GEMM tiling constants ==============================
#define TCM 128
#define TCN 128
#define TCK 64
#define NKCH (EMBED / TCK)        // 16
#define TILE_B  16384             // 128 rows x 64 elems x 2B (128B rows)
#define BUF_B   (4 * TILE_B)
#define GEMM_SMEM (2 * BUF_B)     // 131072 (bf16 3-term)
#define QK_SMEM  (2 * 2 * TILE_B) // 65536  (fp16 1-term)

// ======== fp16 1-term GEMM, fused epilogue -> fp16 [bh][s][64] ==============
// Cf = fp16(scale * (A @ B^T + bias)); A fp16 [M][K], B fp16 [N][K].
__global__ __launch_bounds__(256, 1)
void gemm_f16_kernel(
    const __half* __restrict__ A, const __half* __restrict__ B,
    const float* __restrict__ bias, float scale, __half* __restrict__ Cf)
{
    const uint32_t sb = smem_u32(dyn_smem);
    const int tid  = threadIdx.x;
    const int wid  = tid >> 5;
    const int lane = tid & 31;
    const int wm   = wid & 1;
    const int wn   = wid >> 1;
    const int brow = blockIdx.y * TCM;
    const int bcol = blockIdx.x * TCN;

    const __half* srcs[2] = { A + (size_t)brow * EMBED, B + (size_t)bcol * EMBED };

    const int ld_row  = tid >> 3;
    const int ld_unit = tid & 7;
    auto load_chunk = [&](int c, int buf) {
        const uint32_t bufbase = sb + buf * (2 * TILE_B);
        const int k0 = c * TCK;
#pragma unroll
        for (int t = 0; t < 2; t++) {
#pragma unroll
            for (int it = 0; it < 4; it++) {
                const int row = ld_row + it * 32;
                const uint32_t dst = bufbase + t * TILE_B + row * 128 +
                                     ((ld_unit ^ (row & 7)) << 4);
                cp_async16(dst, srcs[t] + (size_t)row * EMBED + k0 + ld_unit * 8);
            }
        }
    };

    const int quad = lane >> 3;
    const int l7   = lane & 7;
    const int rowA = ((quad & 1) << 3) + l7;
    const int uexA = quad >> 1;
    const int rowB = ((quad >> 1) << 3) + l7;
    const int uexB = quad & 1;

    float acc[4][4][4];
#pragma unroll
    for (int mt = 0; mt < 4; mt++)
#pragma unroll
        for (int nt = 0; nt < 4; nt++)
#pragma unroll
            for (int j = 0; j < 4; j++) acc[mt][nt][j] = 0.0f;

    load_chunk(0, 0);
    cp_commit();
    cp_wait0();
    __syncthreads();

    for (int c = 0; c < NKCH; c++) {
        const int buf = c & 1;
        if (c + 1 < NKCH) { load_chunk(c + 1, buf ^ 1); cp_commit(); }

        const uint32_t TA = sb + buf * (2 * TILE_B);
        const uint32_t TB = TA + TILE_B;

#pragma unroll
        for (int k16 = 0; k16 < 4; k16++) {
            uint32_t a4[4][4], b4[2][4];
            const uint32_t aoff = ((uint32_t)(k16 * 2 + uexA) ^ l7) << 4;
            const uint32_t boff = ((uint32_t)(k16 * 2 + uexB) ^ l7) << 4;
#pragma unroll
            for (int mt = 0; mt < 4; mt++)
                ldmatrix_x4(a4[mt], TA + (wm * 64 + mt * 16 + rowA) * 128 + aoff);
#pragma unroll
            for (int g = 0; g < 2; g++)
                ldmatrix_x4(b4[g], TB + (wn * 32 + g * 16 + rowB) * 128 + boff);
#pragma unroll
            for (int mt = 0; mt < 4; mt++)
#pragma unroll
                for (int nt = 0; nt < 4; nt++) {
                    const int g = nt >> 1, ix = (nt & 1) * 2;
                    mma16816h(acc[mt][nt], a4[mt], b4[g][ix], b4[g][ix + 1]);
                }
        }
        if (c + 1 < NKCH) cp_wait0();
        __syncthreads();
    }

    // fused epilogue: (row, col) -> [b*16+h][s][d] fp16
    const int gid = lane >> 2;
    const int tig = lane & 3;
    const int bb  = brow >> 11;           // SEQ = 2048
#pragma unroll
    for (int mt = 0; mt < 4; mt++) {
        const int r0 = brow + wm * 64 + mt * 16 + gid;
        const int s0 = r0 & (SEQ - 1);
#pragma unroll
        for (int nt = 0; nt < 4; nt++) {
            const int col = bcol + wn * 32 + nt * 8 + tig * 2;
            const int hh  = col >> 6, dd = col & 63;
            const float b0 = bias[col], b1 = bias[col + 1];
            const size_t base = ((size_t)(bb * NHEADS + hh) * SEQ + s0) * HD + dd;
            __half2 v0 = __floats2half2_rn((acc[mt][nt][0] + b0) * scale,
                                           (acc[mt][nt][1] + b1) * scale);
            __half2 v1 = __floats2half2_rn((acc[mt][nt][2] + b0) * scale,
                                           (acc[mt][nt][3] + b1) * scale);
            *(__half2*)&Cf[base] = v0;
            *(__half2*)&Cf[base + (size_t)8 * HD] = v1;
        }
    }
}

// ======== bf16 3-term split GEMM, fp32 epilogue (O projection) ==============
__global__ __launch_bounds__(256, 1)
void gemm_mma_kernel(
    const __nv_bfloat16* __restrict__ Ah, const __nv_bfloat16* __restrict__ Al,
    const __nv_bfloat16* __restrict__ Bh, const __nv_bfloat16* __restrict__ Bl,
    const float* __restrict__ bias, float* __restrict__ C)
{
    const uint32_t sb = smem_u32(dyn_smem);
    const int tid  = threadIdx.x;
    const int wid  = tid >> 5;
    const int lane = tid & 31;
    const int wm   = wid & 1;
    const int wn   = wid >> 1;
    const int brow = blockIdx.y * TCM;
    const int bcol = blockIdx.x * TCN;

    const __nv_bfloat16* srcs[4] = {
        Ah + (size_t)brow * EMBED, Al + (size_t)brow * EMBED,
        Bh + (size_t)bcol * EMBED, Bl + (size_t)bcol * EMBED };

    const int ld_row  = tid >> 3;
    const int ld_unit = tid & 7;
    auto load_chunk = [&](int c, int buf) {
        const uint32_t bufbase = sb + buf * BUF_B;
        const int k0 = c * TCK;
#pragma unroll
        for (int t = 0; t < 4; t++) {
#pragma unroll
            for (int it = 0; it < 4; it++) {
                const int row = ld_row + it * 32;
                const uint32_t dst = bufbase + t * TILE_B + row * 128 +
                                     ((ld_unit ^ (row & 7)) << 4);
                cp_async16(dst, srcs[t] + (size_t)row * EMBED + k0 + ld_unit * 8);
            }
        }
    };

    const int quad = lane >> 3;
    const int l7   = lane & 7;
    const int rowA = ((quad & 1) << 3) + l7;
    const int uexA = quad >> 1;
    const int rowB = ((quad >> 1) << 3) + l7;
    const int uexB = quad & 1;

    float acc[4][4][4];
#pragma unroll
    for (int mt = 0; mt < 4; mt++)
#pragma unroll
        for (int nt = 0; nt < 4; nt++)
#pragma unroll
            for (int j = 0; j < 4; j++) acc[mt][nt][j] = 0.0f;

    load_chunk(0, 0);
    cp_commit();
    cp_wait0();
    __syncthreads();

    for (int c = 0; c < NKCH; c++) {
        const int buf = c & 1;
        if (c + 1 < NKCH) { load_chunk(c + 1, buf ^ 1); cp_commit(); }

        const uint32_t TAh = sb + buf * BUF_B;
        const uint32_t TAl = TAh + TILE_B;
        const uint32_t TBh = TAh + 2 * TILE_B;
        const uint32_t TBl = TAh + 3 * TILE_B;

#pragma unroll
        for (int k16 = 0; k16 < 4; k16++) {
            uint32_t ah[4][4], al[4][4], bh[2][4], bl[2][4];
            const uint32_t aoff = ((uint32_t)(k16 * 2 + uexA) ^ l7) << 4;
            const uint32_t boff = ((uint32_t)(k16 * 2 + uexB) ^ l7) << 4;
#pragma unroll
            for (int mt = 0; mt < 4; mt++) {
                const uint32_t ro = (wm * 64 + mt * 16 + rowA) * 128;
                ldmatrix_x4(ah[mt], TAh + ro + aoff);
                ldmatrix_x4(al[mt], TAl + ro + aoff);
            }
#pragma unroll
            for (int g = 0; g < 2; g++) {
                const uint32_t ro = (wn * 32 + g * 16 + rowB) * 128;
                ldmatrix_x4(bh[g], TBh + ro + boff);
                ldmatrix_x4(bl[g], TBl + ro + boff);
            }
#pragma unroll
            for (int mt = 0; mt < 4; mt++) {
#pragma unroll
                for (int nt = 0; nt < 4; nt++) {
                    const int g = nt >> 1, ix = (nt & 1) * 2;
                    mma16816(acc[mt][nt], ah[mt], bh[g][ix], bh[g][ix + 1]);
                    mma16816(acc[mt][nt], al[mt], bh[g][ix], bh[g][ix + 1]);
                    mma16816(acc[mt][nt], ah[mt], bl[g][ix], bl[g][ix + 1]);
                }
            }
        }
        if (c + 1 < NKCH) cp_wait0();
        __syncthreads();
    }

    const int gid = lane >> 2;
    const int tig = lane & 3;
#pragma unroll
    for (int mt = 0; mt < 4; mt++) {
        const int r0 = brow + wm * 64 + mt * 16 + gid;
#pragma unroll
        for (int nt = 0; nt < 4; nt++) {
            const int col = bcol + wn * 32 + nt * 8 + tig * 2;
            const float b0 = bias[col], b1 = bias[col + 1];
            float2 v0 = { acc[mt][nt][0] + b0, acc[mt][nt][1] + b1 };
            float2 v1 = { acc[mt][nt][2] + b0, acc[mt][nt][3] + b1 };
            *(float2*)&C[(size_t)r0 * EMBED + col] = v0;
            *(float2*)&C[(size_t)(r0 + 8) * EMBED + col] = v1;
        }
    }
}

// ==== bf16 3-term split GEMM, fused fp16 hi/lo epilogue (V projection) ======
__global__ __launch_bounds__(256, 1)
void gemm_mma_v_kernel(
    const __nv_bfloat16* __restrict__ Ah, const __nv_bfloat16* __restrict__ Al,
    const __nv_bfloat16* __restrict__ Bh, const __nv_bfloat16* __restrict__ Bl,
    const float* __restrict__ bias,
    __half* __restrict__ Vh, __half* __restrict__ Vl)
{
    const uint32_t sb = smem_u32(dyn_smem);
    const int tid  = threadIdx.x;
    const int wid  = tid >> 5;
    const int lane = tid & 31;
    const int wm   = wid & 1;
    const int wn   = wid >> 1;
    const int brow = blockIdx.y * TCM;
    const int bcol = blockIdx.x * TCN;

    const __nv_bfloat16* srcs[4] = {
        Ah + (size_t)brow * EMBED, Al + (size_t)brow * EMBED,
        Bh + (size_t)bcol * EMBED, Bl + (size_t)bcol * EMBED };

    const int ld_row  = tid >> 3;
    const int ld_unit = tid & 7;
    auto load_chunk = [&](int c, int buf) {
        const uint32_t bufbase = sb + buf * BUF_B;
        const int k0 = c * TCK;
#pragma unroll
        for (int t = 0; t < 4; t++) {
#pragma unroll
            for (int it = 0; it < 4; it++) {
                const int row = ld_row + it * 32;
                const uint32_t dst = bufbase + t * TILE_B + row * 128 +
                                     ((ld_unit ^ (row & 7)) << 4);
                cp_async16(dst, srcs[t] + (size_t)row * EMBED + k0 + ld_unit * 8);
            }
        }
    };

    const int quad = lane >> 3;
    const int l7   = lane & 7;
    const int rowA = ((quad & 1) << 3) + l7;
    const int uexA = quad >> 1;
    const int rowB = ((quad >> 1) << 3) + l7;
    const int uexB = quad & 1;

    float acc[4][4][4];
#pragma unroll
    for (int mt = 0; mt < 4; mt++)
#pragma unroll
        for (int nt = 0; nt < 4; nt++)
#pragma unroll
            for (int j = 0; j < 4; j++) acc[mt][nt][j] = 0.0f;

    load_chunk(0, 0);
    cp_commit();
    cp_wait0();
    __syncthreads();

    for (int c = 0; c < NKCH; c++) {
        const int buf = c & 1;
        if (c + 1 < NKCH) { load_chunk(c + 1, buf ^ 1); cp_commit(); }

        const uint32_t TAh = sb + buf * BUF_B;
        const uint32_t TAl = TAh + TILE_B;
        const uint32_t TBh = TAh + 2 * TILE_B;
        const uint32_t TBl = TAh + 3 * TILE_B;

#pragma unroll
        for (int k16 = 0; k16 < 4; k16++) {
            uint32_t ah[4][4], al[4][4], bh[2][4], bl[2][4];
            const uint32_t aoff = ((uint32_t)(k16 * 2 + uexA) ^ l7) << 4;
            const uint32_t boff = ((uint32_t)(k16 * 2 + uexB) ^ l7) << 4;
#pragma unroll
            for (int mt = 0; mt < 4; mt++) {
                const uint32_t ro = (wm * 64 + mt * 16 + rowA) * 128;
                ldmatrix_x4(ah[mt], TAh + ro + aoff);
                ldmatrix_x4(al[mt], TAl + ro + aoff);
            }
#pragma unroll
            for (int g = 0; g < 2; g++) {
                const uint32_t ro = (wn * 32 + g * 16 + rowB) * 128;
                ldmatrix_x4(bh[g], TBh + ro + boff);
                ldmatrix_x4(bl[g], TBl + ro + boff);
            }
#pragma unroll
            for (int mt = 0; mt < 4; mt++) {
#pragma unroll
                for (int nt = 0; nt < 4; nt++) {
                    const int g = nt >> 1, ix = (nt & 1) * 2;
                    mma16816(acc[mt][nt], ah[mt], bh[g][ix], bh[g][ix + 1]);
                    mma16816(acc[mt][nt], al[mt], bh[g][ix], bh[g][ix + 1]);
                    mma16816(acc[mt][nt], ah[mt], bl[g][ix], bl[g][ix + 1]);
                }
            }
        }
        if (c + 1 < NKCH) cp_wait0();
        __syncthreads();
    }

    // fused epilogue: fp16 hi/lo split into [b*16+h][s][64]
    const int gid = lane >> 2;
    const int tig = lane & 3;
    const int bb  = brow >> 11;
#pragma unroll
    for (int mt = 0; mt < 4; mt++) {
        const int r0 = brow + wm * 64 + mt * 16 + gid;
        const int s0 = r0 & (SEQ - 1);
#pragma unroll
        for (int nt = 0; nt < 4; nt++) {
            const int col = bcol + wn * 32 + nt * 8 + tig * 2;
            const int hh  = col >> 6, dd = col & 63;
            const size_t base = ((size_t)(bb * NHEADS + hh) * SEQ + s0) * HD + dd;
            const float b0 = bias[col], b1 = bias[col + 1];
            float v00 = acc[mt][nt][0] + b0, v01 = acc[mt][nt][1] + b1;
            float v10 = acc[mt][nt][2] + b0, v11 = acc[mt][nt][3] + b1;
            __half2 h0 = __floats2half2_rn(v00, v01);
            __half2 h1 = __floats2half2_rn(v10, v11);
            __half2 l0 = __floats2half2_rn(v00 - __half2float(h0.x),
                                           v01 - __half2float(h0.y));
            __half2 l1 = __floats2half2_rn(v10 - __half2float(h1.x),
                                           v11 - __half2float(h1.y));
            *(__half2*)&Vh[base] = h0;
            *(__half2*)&Vl[base] = l0;
            *(__half2*)&Vh[base + (size_t)8 * HD] = h1;
            *(__half2*)&Vl[base + (size_t)8 * HD] = l1;
        }
    }
}

// ================= fp16 mma flash attention ==================================
// CTA: 128 q rows x one (b,h). 8 warps, each owns 16 q rows.
// QK: 1-term fp16. PV: 3-term (PhVh + PlVh + PhVl), P split in registers.
// Epilogue writes bf16 hi/lo ctx directly (fused split for O projection).
#define FQ 128
#define FA_BUF 24576
#define FA_SMEM (16384 + 2 * FA_BUF)   // 65536
#define NKVT (SEQ / 64)                // 32

__global__ __launch_bounds__(256, 1) void flash_mma_kernel(
    const __half* __restrict__ Qf, const __half* __restrict__ Kf,
    const __half* __restrict__ Vh, const __half* __restrict__ Vl,
    __nv_bfloat16* __restrict__ Ch, __nv_bfloat16* __restrict__ Cl)
{
    const uint32_t sb = smem_u32(dyn_smem);
    const int tid = threadIdx.x, wid = tid >> 5, lane = tid & 31;
    const int bh = blockIdx.y;
    const int q0 = blockIdx.x * FQ;
    const size_t qoff  = ((size_t)bh * SEQ + q0) * HD;
    const size_t kvoff = (size_t)bh * SEQ * HD;

    // load Q tile (persistent)
    {
        const int u = tid & 7, r0 = tid >> 3;
#pragma unroll
        for (int it = 0; it < 4; it++) {
            const int row = r0 + it * 32;
            cp_async16(sb + row * 128 + (((uint32_t)(u ^ (row & 7))) << 4),
                       Qf + qoff + (size_t)row * HD + u * 8);
        }
    }
    auto load_kv = [&](int t, int buf) {
        const int u = tid & 7, r0 = tid >> 3;
        const size_t off = kvoff + (size_t)t * 64 * HD;
        const uint32_t bb = sb + 16384 + buf * FA_BUF;
        const __half* srcs[3] = { Kf + off, Vh + off, Vl + off };
#pragma unroll
        for (int ts = 0; ts < 3; ts++)
#pragma unroll
            for (int it = 0; it < 2; it++) {
                const int row = r0 + it * 32;
                cp_async16(bb + ts * 8192 + row * 128 +
                           (((uint32_t)(u ^ (row & 7))) << 4),
                           srcs[ts] + (size_t)row * HD + u * 8);
            }
    };
    load_kv(0, 0);
    cp_commit();
    cp_wait0();
    __syncthreads();

    const int quad = lane >> 3, l7 = lane & 7;
    const int rowA = ((quad & 1) << 3) + l7, uexA = quad >> 1;
    const int rowB = ((quad >> 1) << 3) + l7, uexB = quad & 1;
    const int vrow = (((lane >> 3) & 1) << 3) + l7, vuex = lane >> 4;
    const int gid = lane >> 2, tig = lane & 3;

    float m0 = -1e30f, m1 = -1e30f, l0 = 0.0f, l1 = 0.0f;
    float o[8][4];
#pragma unroll
    for (int dt = 0; dt < 8; dt++)
#pragma unroll
        for (int j = 0; j < 4; j++) o[dt][j] = 0.0f;

    for (int t = 0; t < NKVT; t++) {
        const int buf = t & 1;
        if (t + 1 < NKVT) { load_kv(t + 1, buf ^ 1); cp_commit(); }
        const uint32_t kb = sb + 16384 + buf * FA_BUF;

        // ---- scores S = Q @ K^T ----
        float s[8][4];
#pragma unroll
        for (int nt = 0; nt < 8; nt++)
#pragma unroll
            for (int j = 0; j < 4; j++) s[nt][j] = 0.0f;

#pragma unroll
        for (int kc = 0; kc < 4; kc++) {
            uint32_t a4[4];
            ldmatrix_x4(a4, sb + (wid * 16 + rowA) * 128 +
                        (((uint32_t)((kc * 2 + uexA) ^ l7)) << 4));
#pragma unroll
            for (int g = 0; g < 4; g++) {
                uint32_t k4[4];
                ldmatrix_x4(k4, kb + (g * 16 + rowB) * 128 +
                            (((uint32_t)((kc * 2 + uexB) ^ l7)) << 4));
                mma16816h(s[2 * g],     a4, k4[0], k4[1]);
                mma16816h(s[2 * g + 1], a4, k4[2], k4[3]);
            }
        }

        // ---- online softmax (rows gid, gid+8; quad-replicated) ----
        float M0 = -1e30f, M1 = -1e30f;
#pragma unroll
        for (int nt = 0; nt < 8; nt++) {
            M0 = fmaxf(M0, fmaxf(s[nt][0], s[nt][1]));
            M1 = fmaxf(M1, fmaxf(s[nt][2], s[nt][3]));
        }
        M0 = fmaxf(M0, __shfl_xor_sync(0xffffffffu, M0, 1));
        M0 = fmaxf(M0, __shfl_xor_sync(0xffffffffu, M0, 2));
        M1 = fmaxf(M1, __shfl_xor_sync(0xffffffffu, M1, 1));
        M1 = fmaxf(M1, __shfl_xor_sync(0xffffffffu, M1, 2));
        const float mn0 = fmaxf(m0, M0), mn1 = fmaxf(m1, M1);
        const float c0 = __expf(m0 - mn0), c1 = __expf(m1 - mn1);
        m0 = mn0; m1 = mn1;
        float sum0 = 0.0f, sum1 = 0.0f;
#pragma unroll
        for (int nt = 0; nt < 8; nt++) {
            s[nt][0] = __expf(s[nt][0] - mn0);
            s[nt][1] = __expf(s[nt][1] - mn0);
            s[nt][2] = __expf(s[nt][2] - mn1);
            s[nt][3] = __expf(s[nt][3] - mn1);
            sum0 += s[nt][0] + s[nt][1];
            sum1 += s[nt][2] + s[nt][3];
        }
        sum0 += __shfl_xor_sync(0xffffffffu, sum0, 1);
        sum0 += __shfl_xor_sync(0xffffffffu, sum0, 2);
        sum1 += __shfl_xor_sync(0xffffffffu, sum1, 1);
        sum1 += __shfl_xor_sync(0xffffffffu, sum1, 2);
        l0 = l0 * c0 + sum0;
        l1 = l1 * c1 + sum1;
#pragma unroll
        for (int dt = 0; dt < 8; dt++) {
            o[dt][0] *= c0; o[dt][1] *= c0;
            o[dt][2] *= c1; o[dt][3] *= c1;
        }

        // ---- O += P @ V (P split hi/lo in registers, V split in smem) ----
#pragma unroll
        for (int kc = 0; kc < 4; kc++) {
            uint32_t ph[4], pl[4];
#pragma unroll
            for (int h2 = 0; h2 < 4; h2++) {
                const int nt = 2 * kc + (h2 >> 1);
                const int j0 = (h2 & 1) * 2;
                const float p0 = s[nt][j0], p1 = s[nt][j0 + 1];
                __half2 hp = __floats2half2_rn(p0, p1);
                ph[h2] = *(uint32_t*)&hp;
                pl[h2] = packh2(p0 - __half2float(hp.x), p1 - __half2float(hp.y));
            }
#pragma unroll
            for (int g2 = 0; g2 < 4; g2++) {
                uint32_t vh4[4], vl4[4];
                const uint32_t vro = kb + 8192 + (kc * 16 + vrow) * 128 +
                                     (((uint32_t)((g2 * 2 + vuex) ^ l7)) << 4);
                ldmatrix_x4_trans(vh4, vro);
                ldmatrix_x4_trans(vl4, vro + 8192);
                mma16816h(o[2 * g2],     ph, vh4[0], vh4[1]);
                mma16816h(o[2 * g2],     pl, vh4[0], vh4[1]);
                mma16816h(o[2 * g2],     ph, vl4[0], vl4[1]);
                mma16816h(o[2 * g2 + 1], ph, vh4[2], vh4[3]);
                mma16816h(o[2 * g2 + 1], pl, vh4[2], vh4[3]);
                mma16816h(o[2 * g2 + 1], ph, vl4[2], vl4[3]);
            }
        }
        if (t + 1 < NKVT) cp_wait0();
        __syncthreads();
    }

    // ---- fused epilogue: write bf16 hi/lo ctx ----
    const float i0 = 1.0f / l0, i1 = 1.0f / l1;
    const int b = bh >> 4, h = bh & 15;
    const int r0 = q0 + wid * 16 + gid;
    const size_t base = ((size_t)b * SEQ + r0) * EMBED + h * HD;
#pragma unroll
    for (int dt = 0; dt < 8; dt++) {
        const int col = dt * 8 + tig * 2;
        float c00 = o[dt][0] * i0, c01 = o[dt][1] * i0;
        float c10 = o[dt][2] * i1, c11 = o[dt][3] * i1;
        __nv_bfloat16 h00 = __float2bfloat16_rn(c00);
        __nv_bfloat16 h01 = __float2bfloat16_rn(c01);
        __nv_bfloat16 h10 = __float2bfloat16_rn(c10);
        __nv_bfloat16 h11 = __float2bfloat16_rn(c11);
        *(__nv_bfloat162*)&Ch[base + col] = __nv_bfloat162(h00, h01);
        *(__nv_bfloat162*)&Cl[base + col] = __nv_bfloat162(
            __float2bfloat16_rn(c00 - __bfloat162float(h00)),
            __float2bfloat16_rn(c01 - __bfloat162float(h01)));
        *(__nv_bfloat162*)&Ch[base + 8 * EMBED + col] = __nv_bfloat162(h10, h11);
        *(__nv_bfloat162*)&Cl[base + 8 * EMBED + col] = __nv_bfloat162(
            __float2bfloat16_rn(c10 - __bfloat162float(h10)),
            __float2bfloat16_rn(c11 - __bfloat162float(h11)));
    }
}

// ---------------- host launch ----------------
extern "C" void kernel_launch(void* const* d_in, const int* in_sizes, int n_in,
                              void* d_out, int out_size)
{
    const float* x  = (const float*)d_in[0];
    const float* Wq = (const float*)d_in[1];
    const float* bq = (const float*)d_in[2];
    const float* Wk = (const float*)d_in[3];
    const float* bk = (const float*)d_in[4];
    const float* Wv = (const float*)d_in[5];
    const float* bv = (const float*)d_in[6];
    const float* Wo = (const float*)d_in[7];
    const float* bo = (const float*)d_in[8];
    float* out = (float*)d_out;

    __nv_bfloat16 *xh, *xl, *ch, *cl, *wvh, *wvl, *woh, *wol;
    __half *xf, *wqt, *wkt, *qf, *kf, *vhh, *vll;
    cudaGetSymbolAddress((void**)&xh,  g_xh);
    cudaGetSymbolAddress((void**)&xl,  g_xl);
    cudaGetSymbolAddress((void**)&xf,  g_xf);
    cudaGetSymbolAddress((void**)&ch,  g_ch);
    cudaGetSymbolAddress((void**)&cl,  g_cl);
    cudaGetSymbolAddress((void**)&wqt, g_Wqt);
    cudaGetSymbolAddress((void**)&wkt, g_Wkt);
    cudaGetSymbolAddress((void**)&wvh, g_Wvh);
    cudaGetSymbolAddress((void**)&wvl, g_Wvl);
    cudaGetSymbolAddress((void**)&woh, g_Woh);
    cudaGetSymbolAddress((void**)&wol, g_Wol);
    cudaGetSymbolAddress((void**)&qf,  g_Qf);
    cudaGetSymbolAddress((void**)&kf,  g_Kf);
    cudaGetSymbolAddress((void**)&vhh, g_Vhh);
    cudaGetSymbolAddress((void**)&vll, g_Vll);

    cudaFuncSetAttribute(gemm_mma_kernel,
                         cudaFuncAttributeMaxDynamicSharedMemorySize, GEMM_SMEM);
    cudaFuncSetAttribute(gemm_mma_v_kernel,
                         cudaFuncAttributeMaxDynamicSharedMemorySize, GEMM_SMEM);
    cudaFuncSetAttribute(gemm_f16_kernel,
                         cudaFuncAttributeMaxDynamicSharedMemorySize, QK_SMEM);
    cudaFuncSetAttribute(flash_mma_kernel,
                         cudaFuncAttributeMaxDynamicSharedMemorySize, FA_SMEM);

    // 1. operand preparation
    const int n4 = MTOT * EMBED / 4;
    split_x_kernel<<<n4 / 256, 256>>>(x, xh, xl, xf, n4);
    dim3 tg(EMBED / 32, EMBED / 32), tb(32, 8);
    transpose_f16_kernel<<<tg, tb>>>(Wq, wqt);
    transpose_f16_kernel<<<tg, tb>>>(Wk, wkt);
    transpose_split_kernel<<<tg, tb>>>(Wv, wvh, wvl);
    transpose_split_kernel<<<tg, tb>>>(Wo, woh, wol);

    // 2. projections (fused epilogues -> attention layouts)
    dim3 gg(EMBED / TCN, MTOT / TCM);   // (8, 64)
    gemm_f16_kernel<<<gg, 256, QK_SMEM>>>(xf, wqt, bq, 0.125f, qf);
    gemm_f16_kernel<<<gg, 256, QK_SMEM>>>(xf, wkt, bk, 1.0f, kf);
    gemm_mma_v_kernel<<<gg, 256, GEMM_SMEM>>>(xh, xl, wvh, wvl, bv, vhh, vll);

    // 3. flash attention (writes bf16 hi/lo ctx)
    dim3 fg(SEQ / FQ, BH);              // (16, 64)
    flash_mma_kernel<<<fg, 256, FA_SMEM>>>(qf, kf, vhh, vll, ch, cl);

    // 4. output projection
    gemm_mma_kernel<<<gg, 256, GEMM_SMEM>>>(ch, cl, woh, wol, bo, out);
}

// round 17
// speedup vs baseline: 7.8392x; 1.3480x over previous
#include <cuda_runtime.h>
#include <cuda_fp16.h>
#include <math.h>
#include <stdint.h>

#define EMBED   1024
#define NHEADS  16
#define HD      64
#define BATCH   4
#define SEQ     2048
#define MTOT    (BATCH * SEQ)   // 8192
#define BH      (BATCH * NHEADS) // 64

// single dynamic-shared symbol shared by all kernels in this TU
extern __shared__ char dyn_smem[];

// ---------------- scratch (static __device__, no allocation) ----------------
__device__ __half g_xf[(size_t)MTOT * EMBED];
__device__ __half g_ch[(size_t)MTOT * EMBED];
__device__ __half g_cl[(size_t)MTOT * EMBED];

__device__ __half g_Wqt[(size_t)EMBED * EMBED];
__device__ __half g_Wkt[(size_t)EMBED * EMBED];
__device__ __half g_Wvt[(size_t)EMBED * EMBED];
__device__ __half g_Wot[(size_t)EMBED * EMBED];

// fp16 attention operands, layout [b*H+h][s][64]
__device__ __half g_Qf[(size_t)BH * SEQ * HD];
__device__ __half g_Kf[(size_t)BH * SEQ * HD];
__device__ __half g_Vf[(size_t)BH * SEQ * HD];

// ======================= helpers ==============================
__device__ __forceinline__ uint32_t smem_u32(const void* p) {
    uint32_t a;
    asm("{ .reg .u64 t; cvta.to.shared.u64 t, %1; cvt.u32.u64 %0, t; }"
        : "=r"(a) : "l"(p));
    return a;
}
__device__ __forceinline__ void cp_async16(uint32_t dst, const void* src) {
    asm volatile("cp.async.cg.shared.global [%0], [%1], 16;"
                 :: "r"(dst), "l"(src) : "memory");
}
__device__ __forceinline__ void cp_commit() {
    asm volatile("cp.async.commit_group;" ::: "memory");
}
__device__ __forceinline__ void cp_wait0() {
    asm volatile("cp.async.wait_group 0;" ::: "memory");
}
__device__ __forceinline__ void ldmatrix_x4(uint32_t* r, uint32_t addr) {
    asm volatile("ldmatrix.sync.aligned.m8n8.x4.shared.b16 {%0,%1,%2,%3}, [%4];"
                 : "=r"(r[0]), "=r"(r[1]), "=r"(r[2]), "=r"(r[3]) : "r"(addr));
}
__device__ __forceinline__ void ldmatrix_x4_trans(uint32_t* r, uint32_t addr) {
    asm volatile("ldmatrix.sync.aligned.m8n8.x4.trans.shared.b16 {%0,%1,%2,%3}, [%4];"
                 : "=r"(r[0]), "=r"(r[1]), "=r"(r[2]), "=r"(r[3]) : "r"(addr));
}
__device__ __forceinline__ void mma16816h(float* d, const uint32_t* a,
                                          uint32_t b0, uint32_t b1) {
    asm volatile(
        "mma.sync.aligned.m16n8k16.row.col.f32.f16.f16.f32 "
        "{%0,%1,%2,%3}, {%4,%5,%6,%7}, {%8,%9}, {%0,%1,%2,%3};"
        : "+f"(d[0]), "+f"(d[1]), "+f"(d[2]), "+f"(d[3])
        : "r"(a[0]), "r"(a[1]), "r"(a[2]), "r"(a[3]), "r"(b0), "r"(b1));
}
__device__ __forceinline__ uint32_t packh2(float lo, float hi) {
    __half2 h = __floats2half2_rn(lo, hi);
    return *(uint32_t*)&h;
}

// ======================= prep kernels =======================================
// x fp32 -> fp16
__global__ __launch_bounds__(256) void convert_f16_kernel(
    const float* __restrict__ in, __half* __restrict__ out, int n4)
{
    int i = blockIdx.x * 256 + threadIdx.x;
    if (i >= n4) return;
    float4 v = ((const float4*)in)[i];
    __half2* fp = (__half2*)out;
    fp[2*i + 0] = __floats2half2_rn(v.x, v.y);
    fp[2*i + 1] = __floats2half2_rn(v.z, v.w);
}

// W[K][N] fp32 -> Wt[N][K] fp16 (transpose)
__global__ __launch_bounds__(256) void transpose_f16_kernel(
    const float* __restrict__ W, __half* __restrict__ out)
{
    __shared__ float t[32][33];
    int tx = threadIdx.x, ty = threadIdx.y;
    int n0 = blockIdx.x * 32;
    int k0 = blockIdx.y * 32;
#pragma unroll
    for (int j = 0; j < 4; j++)
        t[ty + j * 8][tx] = W[(size_t)(k0 + ty + j * 8) * EMBED + n0 + tx];
    __syncthreads();
#pragma unroll
    for (int j = 0; j < 4; j++) {
        float v = t[tx][ty + j * 8];
        out[(size_t)(n0 + ty + j * 8) * EMBED + k0 + tx] = __float2half_rn(v);
    }
}

// ======================= GEMM tiling constants ==============================
#define TCM 128
#define TCN 128
#define TCK 64
#define NKCH (EMBED / TCK)        // 16
#define TILE_B  16384             // 128 rows x 64 elems x 2B (128B rows)
#define QK_SMEM (2 * 2 * TILE_B)  // 65536  (fp16 1-term)
#define O_SMEM  (2 * 3 * TILE_B)  // 98304  (fp16 2-term)

// ======== fp16 1-term GEMM, fused epilogue -> fp16 [bh][s][64] ==============
// Cf = fp16(scale * (A @ B^T + bias)); A fp16 [M][K], B fp16 [N][K].
__global__ __launch_bounds__(256, 1)
void gemm_f16_kernel(
    const __half* __restrict__ A, const __half* __restrict__ B,
    const float* __restrict__ bias, float scale, __half* __restrict__ Cf)
{
    const uint32_t sb = smem_u32(dyn_smem);
    const int tid  = threadIdx.x;
    const int wid  = tid >> 5;
    const int lane = tid & 31;
    const int wm   = wid & 1;
    const int wn   = wid >> 1;
    const int brow = blockIdx.y * TCM;
    const int bcol = blockIdx.x * TCN;

    const __half* srcs[2] = { A + (size_t)brow * EMBED, B + (size_t)bcol * EMBED };

    const int ld_row  = tid >> 3;
    const int ld_unit = tid & 7;
    auto load_chunk = [&](int c, int buf) {
        const uint32_t bufbase = sb + buf * (2 * TILE_B);
        const int k0 = c * TCK;
#pragma unroll
        for (int t = 0; t < 2; t++) {
#pragma unroll
            for (int it = 0; it < 4; it++) {
                const int row = ld_row + it * 32;
                const uint32_t dst = bufbase + t * TILE_B + row * 128 +
                                     ((ld_unit ^ (row & 7)) << 4);
                cp_async16(dst, srcs[t] + (size_t)row * EMBED + k0 + ld_unit * 8);
            }
        }
    };

    const int quad = lane >> 3;
    const int l7   = lane & 7;
    const int rowA = ((quad & 1) << 3) + l7;
    const int uexA = quad >> 1;
    const int rowB = ((quad >> 1) << 3) + l7;
    const int uexB = quad & 1;

    float acc[4][4][4];
#pragma unroll
    for (int mt = 0; mt < 4; mt++)
#pragma unroll
        for (int nt = 0; nt < 4; nt++)
#pragma unroll
            for (int j = 0; j < 4; j++) acc[mt][nt][j] = 0.0f;

    load_chunk(0, 0);
    cp_commit();
    cp_wait0();
    __syncthreads();

    for (int c = 0; c < NKCH; c++) {
        const int buf = c & 1;
        if (c + 1 < NKCH) { load_chunk(c + 1, buf ^ 1); cp_commit(); }

        const uint32_t TA = sb + buf * (2 * TILE_B);
        const uint32_t TB = TA + TILE_B;

#pragma unroll
        for (int k16 = 0; k16 < 4; k16++) {
            uint32_t a4[4][4], b4[2][4];
            const uint32_t aoff = ((uint32_t)(k16 * 2 + uexA) ^ l7) << 4;
            const uint32_t boff = ((uint32_t)(k16 * 2 + uexB) ^ l7) << 4;
#pragma unroll
            for (int mt = 0; mt < 4; mt++)
                ldmatrix_x4(a4[mt], TA + (wm * 64 + mt * 16 + rowA) * 128 + aoff);
#pragma unroll
            for (int g = 0; g < 2; g++)
                ldmatrix_x4(b4[g], TB + (wn * 32 + g * 16 + rowB) * 128 + boff);
#pragma unroll
            for (int mt = 0; mt < 4; mt++)
#pragma unroll
                for (int nt = 0; nt < 4; nt++) {
                    const int g = nt >> 1, ix = (nt & 1) * 2;
                    mma16816h(acc[mt][nt], a4[mt], b4[g][ix], b4[g][ix + 1]);
                }
        }
        if (c + 1 < NKCH) cp_wait0();
        __syncthreads();
    }

    // fused epilogue: (row, col) -> [b*16+h][s][d] fp16
    const int gid = lane >> 2;
    const int tig = lane & 3;
    const int bb  = brow >> 11;           // SEQ = 2048
#pragma unroll
    for (int mt = 0; mt < 4; mt++) {
        const int r0 = brow + wm * 64 + mt * 16 + gid;
        const int s0 = r0 & (SEQ - 1);
#pragma unroll
        for (int nt = 0; nt < 4; nt++) {
            const int col = bcol + wn * 32 + nt * 8 + tig * 2;
            const int hh  = col >> 6, dd = col & 63;
            const float b0 = bias[col], b1 = bias[col + 1];
            const size_t base = ((size_t)(bb * NHEADS + hh) * SEQ + s0) * HD + dd;
            __half2 v0 = __floats2half2_rn((acc[mt][nt][0] + b0) * scale,
                                           (acc[mt][nt][1] + b1) * scale);
            __half2 v1 = __floats2half2_rn((acc[mt][nt][2] + b0) * scale,
                                           (acc[mt][nt][3] + b1) * scale);
            *(__half2*)&Cf[base] = v0;
            *(__half2*)&Cf[base + (size_t)8 * HD] = v1;
        }
    }
}

// ======== fp16 2-term GEMM (A split hi/lo), fp32 epilogue (O projection) ====
// C = (Ah+Al) @ B^T + bias
__global__ __launch_bounds__(256, 1)
void gemm_f16_o_kernel(
    const __half* __restrict__ Ah, const __half* __restrict__ Al,
    const __half* __restrict__ B,
    const float* __restrict__ bias, float* __restrict__ C)
{
    const uint32_t sb = smem_u32(dyn_smem);
    const int tid  = threadIdx.x;
    const int wid  = tid >> 5;
    const int lane = tid & 31;
    const int wm   = wid & 1;
    const int wn   = wid >> 1;
    const int brow = blockIdx.y * TCM;
    const int bcol = blockIdx.x * TCN;

    const __half* srcs[3] = { Ah + (size_t)brow * EMBED, Al + (size_t)brow * EMBED,
                              B + (size_t)bcol * EMBED };

    const int ld_row  = tid >> 3;
    const int ld_unit = tid & 7;
    auto load_chunk = [&](int c, int buf) {
        const uint32_t bufbase = sb + buf * (3 * TILE_B);
        const int k0 = c * TCK;
#pragma unroll
        for (int t = 0; t < 3; t++) {
#pragma unroll
            for (int it = 0; it < 4; it++) {
                const int row = ld_row + it * 32;
                const uint32_t dst = bufbase + t * TILE_B + row * 128 +
                                     ((ld_unit ^ (row & 7)) << 4);
                cp_async16(dst, srcs[t] + (size_t)row * EMBED + k0 + ld_unit * 8);
            }
        }
    };

    const int quad = lane >> 3;
    const int l7   = lane & 7;
    const int rowA = ((quad & 1) << 3) + l7;
    const int uexA = quad >> 1;
    const int rowB = ((quad >> 1) << 3) + l7;
    const int uexB = quad & 1;

    float acc[4][4][4];
#pragma unroll
    for (int mt = 0; mt < 4; mt++)
#pragma unroll
        for (int nt = 0; nt < 4; nt++)
#pragma unroll
            for (int j = 0; j < 4; j++) acc[mt][nt][j] = 0.0f;

    load_chunk(0, 0);
    cp_commit();
    cp_wait0();
    __syncthreads();

    for (int c = 0; c < NKCH; c++) {
        const int buf = c & 1;
        if (c + 1 < NKCH) { load_chunk(c + 1, buf ^ 1); cp_commit(); }

        const uint32_t TAh = sb + buf * (3 * TILE_B);
        const uint32_t TAl = TAh + TILE_B;
        const uint32_t TB  = TAh + 2 * TILE_B;

#pragma unroll
        for (int k16 = 0; k16 < 4; k16++) {
            uint32_t ah[4][4], al[4][4], b4[2][4];
            const uint32_t aoff = ((uint32_t)(k16 * 2 + uexA) ^ l7) << 4;
            const uint32_t boff = ((uint32_t)(k16 * 2 + uexB) ^ l7) << 4;
#pragma unroll
            for (int mt = 0; mt < 4; mt++) {
                const uint32_t ro = (wm * 64 + mt * 16 + rowA) * 128;
                ldmatrix_x4(ah[mt], TAh + ro + aoff);
                ldmatrix_x4(al[mt], TAl + ro + aoff);
            }
#pragma unroll
            for (int g = 0; g < 2; g++)
                ldmatrix_x4(b4[g], TB + (wn * 32 + g * 16 + rowB) * 128 + boff);
#pragma unroll
            for (int mt = 0; mt < 4; mt++)
#pragma unroll
                for (int nt = 0; nt < 4; nt++) {
                    const int g = nt >> 1, ix = (nt & 1) * 2;
                    mma16816h(acc[mt][nt], ah[mt], b4[g][ix], b4[g][ix + 1]);
                    mma16816h(acc[mt][nt], al[mt], b4[g][ix], b4[g][ix + 1]);
                }
        }
        if (c + 1 < NKCH) cp_wait0();
        __syncthreads();
    }

    const int gid = lane >> 2;
    const int tig = lane & 3;
#pragma unroll
    for (int mt = 0; mt < 4; mt++) {
        const int r0 = brow + wm * 64 + mt * 16 + gid;
#pragma unroll
        for (int nt = 0; nt < 4; nt++) {
            const int col = bcol + wn * 32 + nt * 8 + tig * 2;
            const float b0 = bias[col], b1 = bias[col + 1];
            float2 v0 = { acc[mt][nt][0] + b0, acc[mt][nt][1] + b1 };
            float2 v1 = { acc[mt][nt][2] + b0, acc[mt][nt][3] + b1 };
            *(float2*)&C[(size_t)r0 * EMBED + col] = v0;
            *(float2*)&C[(size_t)(r0 + 8) * EMBED + col] = v1;
        }
    }
}

// ================= fp16 mma flash attention ==================================
// CTA: 128 q rows x one (b,h). 8 warps, each owns 16 q rows.
// QK: 1-term fp16. PV: 2-term (PhV + PlV), P split in registers.
// Epilogue writes fp16 hi/lo ctx directly (fused split for O projection).
#define FQ 128
#define FA_BUF 16384
#define FA_SMEM (16384 + 2 * FA_BUF)   // 49152
#define NKVT (SEQ / 64)                // 32

__global__ __launch_bounds__(256, 1) void flash_mma_kernel(
    const __half* __restrict__ Qf, const __half* __restrict__ Kf,
    const __half* __restrict__ Vf,
    __half* __restrict__ Ch, __half* __restrict__ Cl)
{
    const uint32_t sb = smem_u32(dyn_smem);
    const int tid = threadIdx.x, wid = tid >> 5, lane = tid & 31;
    const int bh = blockIdx.y;
    const int q0 = blockIdx.x * FQ;
    const size_t qoff  = ((size_t)bh * SEQ + q0) * HD;
    const size_t kvoff = (size_t)bh * SEQ * HD;

    // load Q tile (persistent)
    {
        const int u = tid & 7, r0 = tid >> 3;
#pragma unroll
        for (int it = 0; it < 4; it++) {
            const int row = r0 + it * 32;
            cp_async16(sb + row * 128 + (((uint32_t)(u ^ (row & 7))) << 4),
                       Qf + qoff + (size_t)row * HD + u * 8);
        }
    }
    auto load_kv = [&](int t, int buf) {
        const int u = tid & 7, r0 = tid >> 3;
        const size_t off = kvoff + (size_t)t * 64 * HD;
        const uint32_t bb = sb + 16384 + buf * FA_BUF;
        const __half* srcs[2] = { Kf + off, Vf + off };
#pragma unroll
        for (int ts = 0; ts < 2; ts++)
#pragma unroll
            for (int it = 0; it < 2; it++) {
                const int row = r0 + it * 32;
                cp_async16(bb + ts * 8192 + row * 128 +
                           (((uint32_t)(u ^ (row & 7))) << 4),
                           srcs[ts] + (size_t)row * HD + u * 8);
            }
    };
    load_kv(0, 0);
    cp_commit();
    cp_wait0();
    __syncthreads();

    const int quad = lane >> 3, l7 = lane & 7;
    const int rowA = ((quad & 1) << 3) + l7, uexA = quad >> 1;
    const int rowB = ((quad >> 1) << 3) + l7, uexB = quad & 1;
    const int vrow = (((lane >> 3) & 1) << 3) + l7, vuex = lane >> 4;
    const int gid = lane >> 2, tig = lane & 3;

    float m0 = -1e30f, m1 = -1e30f, l0 = 0.0f, l1 = 0.0f;
    float o[8][4];
#pragma unroll
    for (int dt = 0; dt < 8; dt++)
#pragma unroll
        for (int j = 0; j < 4; j++) o[dt][j] = 0.0f;

    for (int t = 0; t < NKVT; t++) {
        const int buf = t & 1;
        if (t + 1 < NKVT) { load_kv(t + 1, buf ^ 1); cp_commit(); }
        const uint32_t kb = sb + 16384 + buf * FA_BUF;

        // ---- scores S = Q @ K^T ----
        float s[8][4];
#pragma unroll
        for (int nt = 0; nt < 8; nt++)
#pragma unroll
            for (int j = 0; j < 4; j++) s[nt][j] = 0.0f;

#pragma unroll
        for (int kc = 0; kc < 4; kc++) {
            uint32_t a4[4];
            ldmatrix_x4(a4, sb + (wid * 16 + rowA) * 128 +
                        (((uint32_t)((kc * 2 + uexA) ^ l7)) << 4));
#pragma unroll
            for (int g = 0; g < 4; g++) {
                uint32_t k4[4];
                ldmatrix_x4(k4, kb + (g * 16 + rowB) * 128 +
                            (((uint32_t)((kc * 2 + uexB) ^ l7)) << 4));
                mma16816h(s[2 * g],     a4, k4[0], k4[1]);
                mma16816h(s[2 * g + 1], a4, k4[2], k4[3]);
            }
        }

        // ---- online softmax (rows gid, gid+8; quad-replicated) ----
        float M0 = -1e30f, M1 = -1e30f;
#pragma unroll
        for (int nt = 0; nt < 8; nt++) {
            M0 = fmaxf(M0, fmaxf(s[nt][0], s[nt][1]));
            M1 = fmaxf(M1, fmaxf(s[nt][2], s[nt][3]));
        }
        M0 = fmaxf(M0, __shfl_xor_sync(0xffffffffu, M0, 1));
        M0 = fmaxf(M0, __shfl_xor_sync(0xffffffffu, M0, 2));
        M1 = fmaxf(M1, __shfl_xor_sync(0xffffffffu, M1, 1));
        M1 = fmaxf(M1, __shfl_xor_sync(0xffffffffu, M1, 2));
        const float mn0 = fmaxf(m0, M0), mn1 = fmaxf(m1, M1);
        const float c0 = __expf(m0 - mn0), c1 = __expf(m1 - mn1);
        m0 = mn0; m1 = mn1;
        float sum0 = 0.0f, sum1 = 0.0f;
#pragma unroll
        for (int nt = 0; nt < 8; nt++) {
            s[nt][0] = __expf(s[nt][0] - mn0);
            s[nt][1] = __expf(s[nt][1] - mn0);
            s[nt][2] = __expf(s[nt][2] - mn1);
            s[nt][3] = __expf(s[nt][3] - mn1);
            sum0 += s[nt][0] + s[nt][1];
            sum1 += s[nt][2] + s[nt][3];
        }
        sum0 += __shfl_xor_sync(0xffffffffu, sum0, 1);
        sum0 += __shfl_xor_sync(0xffffffffu, sum0, 2);
        sum1 += __shfl_xor_sync(0xffffffffu, sum1, 1);
        sum1 += __shfl_xor_sync(0xffffffffu, sum1, 2);
        l0 = l0 * c0 + sum0;
        l1 = l1 * c1 + sum1;
#pragma unroll
        for (int dt = 0; dt < 8; dt++) {
            o[dt][0] *= c0; o[dt][1] *= c0;
            o[dt][2] *= c1; o[dt][3] *= c1;
        }

        // ---- O += P @ V (P split hi/lo in registers) ----
#pragma unroll
        for (int kc = 0; kc < 4; kc++) {
            uint32_t ph[4], pl[4];
#pragma unroll
            for (int h2 = 0; h2 < 4; h2++) {
                const int nt = 2 * kc + (h2 >> 1);
                const int j0 = (h2 & 1) * 2;
                const float p0 = s[nt][j0], p1 = s[nt][j0 + 1];
                __half2 hp = __floats2half2_rn(p0, p1);
                ph[h2] = *(uint32_t*)&hp;
                pl[h2] = packh2(p0 - __half2float(hp.x), p1 - __half2float(hp.y));
            }
#pragma unroll
            for (int g2 = 0; g2 < 4; g2++) {
                uint32_t vh4[4];
                const uint32_t vro = kb + 8192 + (kc * 16 + vrow) * 128 +
                                     (((uint32_t)((g2 * 2 + vuex) ^ l7)) << 4);
                ldmatrix_x4_trans(vh4, vro);
                mma16816h(o[2 * g2],     ph, vh4[0], vh4[1]);
                mma16816h(o[2 * g2],     pl, vh4[0], vh4[1]);
                mma16816h(o[2 * g2 + 1], ph, vh4[2], vh4[3]);
                mma16816h(o[2 * g2 + 1], pl, vh4[2], vh4[3]);
            }
        }
        if (t + 1 < NKVT) cp_wait0();
        __syncthreads();
    }

    // ---- fused epilogue: write fp16 hi/lo ctx ----
    const float i0 = 1.0f / l0, i1 = 1.0f / l1;
    const int b = bh >> 4, h = bh & 15;
    const int r0 = q0 + wid * 16 + gid;
    const size_t base = ((size_t)b * SEQ + r0) * EMBED + h * HD;
#pragma unroll
    for (int dt = 0; dt < 8; dt++) {
        const int col = dt * 8 + tig * 2;
        float c00 = o[dt][0] * i0, c01 = o[dt][1] * i0;
        float c10 = o[dt][2] * i1, c11 = o[dt][3] * i1;
        __half2 h0 = __floats2half2_rn(c00, c01);
        __half2 h1 = __floats2half2_rn(c10, c11);
        __half2 e0 = __floats2half2_rn(c00 - __half2float(h0.x),
                                       c01 - __half2float(h0.y));
        __half2 e1 = __floats2half2_rn(c10 - __half2float(h1.x),
                                       c11 - __half2float(h1.y));
        *(__half2*)&Ch[base + col] = h0;
        *(__half2*)&Cl[base + col] = e0;
        *(__half2*)&Ch[base + 8 * EMBED + col] = h1;
        *(__half2*)&Cl[base + 8 * EMBED + col] = e1;
    }
}

// ---------------- host launch ----------------
extern "C" void kernel_launch(void* const* d_in, const int* in_sizes, int n_in,
                              void* d_out, int out_size)
{
    const float* x  = (const float*)d_in[0];
    const float* Wq = (const float*)d_in[1];
    const float* bq = (const float*)d_in[2];
    const float* Wk = (const float*)d_in[3];
    const float* bk = (const float*)d_in[4];
    const float* Wv = (const float*)d_in[5];
    const float* bv = (const float*)d_in[6];
    const float* Wo = (const float*)d_in[7];
    const float* bo = (const float*)d_in[8];
    float* out = (float*)d_out;

    __half *xf, *ch, *cl, *wqt, *wkt, *wvt, *wot, *qf, *kf, *vf;
    cudaGetSymbolAddress((void**)&xf,  g_xf);
    cudaGetSymbolAddress((void**)&ch,  g_ch);
    cudaGetSymbolAddress((void**)&cl,  g_cl);
    cudaGetSymbolAddress((void**)&wqt, g_Wqt);
    cudaGetSymbolAddress((void**)&wkt, g_Wkt);
    cudaGetSymbolAddress((void**)&wvt, g_Wvt);
    cudaGetSymbolAddress((void**)&wot, g_Wot);
    cudaGetSymbolAddress((void**)&qf,  g_Qf);
    cudaGetSymbolAddress((void**)&kf,  g_Kf);
    cudaGetSymbolAddress((void**)&vf,  g_Vf);

    cudaFuncSetAttribute(gemm_f16_kernel,
                         cudaFuncAttributeMaxDynamicSharedMemorySize, QK_SMEM);
    cudaFuncSetAttribute(gemm_f16_o_kernel,
                         cudaFuncAttributeMaxDynamicSharedMemorySize, O_SMEM);
    cudaFuncSetAttribute(flash_mma_kernel,
                         cudaFuncAttributeMaxDynamicSharedMemorySize, FA_SMEM);

    // 1. operand preparation
    const int n4 = MTOT * EMBED / 4;
    convert_f16_kernel<<<n4 / 256, 256>>>(x, xf, n4);
    dim3 tg(EMBED / 32, EMBED / 32), tb(32, 8);
    transpose_f16_kernel<<<tg, tb>>>(Wq, wqt);
    transpose_f16_kernel<<<tg, tb>>>(Wk, wkt);
    transpose_f16_kernel<<<tg, tb>>>(Wv, wvt);
    transpose_f16_kernel<<<tg, tb>>>(Wo, wot);

    // 2. projections (fused epilogues -> attention layouts)
    dim3 gg(EMBED / TCN, MTOT / TCM);   // (8, 64)
    gemm_f16_kernel<<<gg, 256, QK_SMEM>>>(xf, wqt, bq, 0.125f, qf);
    gemm_f16_kernel<<<gg, 256, QK_SMEM>>>(xf, wkt, bk, 1.0f, kf);
    gemm_f16_kernel<<<gg, 256, QK_SMEM>>>(xf, wvt, bv, 1.0f, vf);

    // 3. flash attention (writes fp16 hi/lo ctx)
    dim3 fg(SEQ / FQ, BH);              // (16, 64)
    flash_mma_kernel<<<fg, 256, FA_SMEM>>>(qf, kf, vf, ch, cl);

    // 4. output projection (2-term fp16)
    gemm_f16_o_kernel<<<gg, 256, O_SMEM>>>(ch, cl, wot, bo, out);
}